// round 9
// baseline (speedup 1.0000x reference)
#include <cuda_runtime.h>
#include <cstdint>

// Problem constants
#define B_    32
#define TH    256
#define TQ    64
#define DIN   256
#define DD    256
#define KD    256
#define NTOT  (B_ * TH)   // 8192 global t

// Scratch (allocation-free rule: __device__ globals)
__device__ float g_kpT[DD * NTOT];     // 8 MB: [d][b*TH + t], ld = 8192
__device__ float g_qp [B_ * TQ * DD];  // 2 MB: [q_global][d]

__device__ __forceinline__ float tanh_fast(float x) {
    float y;
    asm("tanh.approx.f32 %0, %1;" : "=f"(y) : "f"(x));
    return y;
}

// ---- tf32 mma helpers ----
__device__ __forceinline__ unsigned f2tf(float f) {
    unsigned u; asm("cvt.rna.tf32.f32 %0, %1;" : "=r"(u) : "f"(f)); return u;
}
__device__ __forceinline__ void mma_tf32(
    float c[4], unsigned a0, unsigned a1, unsigned a2, unsigned a3,
    unsigned b0, unsigned b1)
{
    asm("mma.sync.aligned.m16n8k8.row.col.f32.tf32.tf32.f32 "
        "{%0,%1,%2,%3}, {%4,%5,%6,%7}, {%8,%9}, {%0,%1,%2,%3};"
        : "+f"(c[0]), "+f"(c[1]), "+f"(c[2]), "+f"(c[3])
        : "r"(a0), "r"(a1), "r"(a2), "r"(a3), "r"(b0), "r"(b1));
}

// ---------------------------------------------------------------------------
// Kernel 1: tensor-core (tf32) projection GEMMs.
//   GEMM1 (blocks 0..127):   g_kpT[d][n] = sum_k w1[d,k] * inputs[n,k]
//                            M=256 (d), N=8192 (n = b*TH+t)
//   GEMM2 (blocks 128..159): g_qp[q][d]  = sum_k state[q,k] * w2[d,k]
//                            M=2048 (q), N=256 (d)
// Both: A row-major (m,k); B source row-major (n,k) == col-major (k,n).
// Block tile 128x128, BK=16 double-buffered, 8 warps (4m x 2n), warp 32x64.
// Fragments per mma m16n8k8 tf32 (g = lane>>2, tig = lane&3):
//   A: a0=(g,tig) a1=(g+8,tig) a2=(g,tig+4) a3=(g+8,tig+4)
//   B: b0=(k=tig,n=g) b1=(k=tig+4,n=g)
//   C: c0=(g,2tig) c1=(g,2tig+1) c2=(g+8,2tig) c3=(g+8,2tig+1)
// ---------------------------------------------------------------------------
#define BM   128
#define BN   128
#define BK   16
#define SPAD 20   // floats per staged row: 80 B (16B-aligned), conflict-free

__global__ __launch_bounds__(256) void proj_tc(
    const float* __restrict__ inputs, const float* __restrict__ state,
    const float* __restrict__ w1, const float* __restrict__ w2)
{
    __shared__ __align__(16) unsigned As[2][BM * SPAD];  // 20 KB
    __shared__ __align__(16) unsigned Bs[2][BN * SPAD];  // 20 KB

    const float* A;
    const float* Bsrc;
    float* C;
    int m0, n0;
    size_t ldc;
    int id = blockIdx.x;
    if (id < 128) {            // GEMM1: kpT
        A = w1; Bsrc = inputs; C = g_kpT; ldc = NTOT;
        m0 = (id & 1) * BM;    // 2 m-tiles
        n0 = (id >> 1) * BN;   // 64 n-tiles
    } else {                   // GEMM2: qp
        id -= 128;
        A = state; Bsrc = w2; C = g_qp; ldc = DD;
        m0 = (id & 15) * BM;   // 16 m-tiles
        n0 = (id >> 4) * BN;   // 2 n-tiles
    }

    const int tid  = threadIdx.x;
    const int warp = tid >> 5, lane = tid & 31;
    const int g    = lane >> 2, tig = lane & 3;
    const int wm   = (warp >> 1) * 32;   // warp m-offset (4 groups)
    const int wn   = (warp & 1) * 64;    // warp n-offset (2 groups)

    // staging: thread owns row srow = tid>>1, k-halves sk4 / sk4+4
    const int srow = tid >> 1;
    const int sk4  = (tid & 1) * 8;
    const float* pa = A    + (size_t)(m0 + srow) * KD + sk4;
    const float* pb = Bsrc + (size_t)(n0 + srow) * KD + sk4;

    float acc[2][8][4];
#pragma unroll
    for (int mt = 0; mt < 2; mt++)
#pragma unroll
        for (int nt = 0; nt < 8; nt++)
#pragma unroll
            for (int i = 0; i < 4; i++) acc[mt][nt][i] = 0.f;

    float4 fa0, fa1, fb0, fb1;

    // prologue: chunk 0 -> buf0, prefetch chunk 1
    fa0 = *(const float4*)&pa[0];  fa1 = *(const float4*)&pa[4];
    fb0 = *(const float4*)&pb[0];  fb1 = *(const float4*)&pb[4];
    {
        uint4 u;
        u.x = f2tf(fa0.x); u.y = f2tf(fa0.y); u.z = f2tf(fa0.z); u.w = f2tf(fa0.w);
        *(uint4*)&As[0][srow * SPAD + sk4] = u;
        u.x = f2tf(fa1.x); u.y = f2tf(fa1.y); u.z = f2tf(fa1.z); u.w = f2tf(fa1.w);
        *(uint4*)&As[0][srow * SPAD + sk4 + 4] = u;
        u.x = f2tf(fb0.x); u.y = f2tf(fb0.y); u.z = f2tf(fb0.z); u.w = f2tf(fb0.w);
        *(uint4*)&Bs[0][srow * SPAD + sk4] = u;
        u.x = f2tf(fb1.x); u.y = f2tf(fb1.y); u.z = f2tf(fb1.z); u.w = f2tf(fb1.w);
        *(uint4*)&Bs[0][srow * SPAD + sk4 + 4] = u;
    }
    fa0 = *(const float4*)&pa[BK];  fa1 = *(const float4*)&pa[BK + 4];
    fb0 = *(const float4*)&pb[BK];  fb1 = *(const float4*)&pb[BK + 4];
    __syncthreads();

    for (int c = 0; c < KD / BK; c++) {       // 16 chunks
        const int cur = c & 1, nxt = cur ^ 1;
        if (c < 15) {
            uint4 u;
            u.x = f2tf(fa0.x); u.y = f2tf(fa0.y); u.z = f2tf(fa0.z); u.w = f2tf(fa0.w);
            *(uint4*)&As[nxt][srow * SPAD + sk4] = u;
            u.x = f2tf(fa1.x); u.y = f2tf(fa1.y); u.z = f2tf(fa1.z); u.w = f2tf(fa1.w);
            *(uint4*)&As[nxt][srow * SPAD + sk4 + 4] = u;
            u.x = f2tf(fb0.x); u.y = f2tf(fb0.y); u.z = f2tf(fb0.z); u.w = f2tf(fb0.w);
            *(uint4*)&Bs[nxt][srow * SPAD + sk4] = u;
            u.x = f2tf(fb1.x); u.y = f2tf(fb1.y); u.z = f2tf(fb1.z); u.w = f2tf(fb1.w);
            *(uint4*)&Bs[nxt][srow * SPAD + sk4 + 4] = u;
            if (c < 14) {
                const int ko = (c + 2) * BK;
                fa0 = *(const float4*)&pa[ko];  fa1 = *(const float4*)&pa[ko + 4];
                fb0 = *(const float4*)&pb[ko];  fb1 = *(const float4*)&pb[ko + 4];
            }
        }
#pragma unroll
        for (int ks = 0; ks < 2; ks++) {      // two k=8 steps per chunk
            const int kb = ks * 8;
            unsigned a[2][4], b[8][2];
#pragma unroll
            for (int mt = 0; mt < 2; mt++) {
                const int r = wm + mt * 16 + g;
                a[mt][0] = As[cur][r * SPAD + kb + tig];
                a[mt][1] = As[cur][(r + 8) * SPAD + kb + tig];
                a[mt][2] = As[cur][r * SPAD + kb + tig + 4];
                a[mt][3] = As[cur][(r + 8) * SPAD + kb + tig + 4];
            }
#pragma unroll
            for (int nt = 0; nt < 8; nt++) {
                const int n = wn + nt * 8 + g;
                b[nt][0] = Bs[cur][n * SPAD + kb + tig];
                b[nt][1] = Bs[cur][n * SPAD + kb + tig + 4];
            }
#pragma unroll
            for (int mt = 0; mt < 2; mt++)
#pragma unroll
                for (int nt = 0; nt < 8; nt++)
                    mma_tf32(acc[mt][nt],
                             a[mt][0], a[mt][1], a[mt][2], a[mt][3],
                             b[nt][0], b[nt][1]);
        }
        __syncthreads();
    }

    // store C
#pragma unroll
    for (int mt = 0; mt < 2; mt++) {
        const int row = m0 + wm + mt * 16 + g;
#pragma unroll
        for (int nt = 0; nt < 8; nt++) {
            const int col = n0 + wn + nt * 8 + 2 * tig;
            float2 v0 = make_float2(acc[mt][nt][0], acc[mt][nt][1]);
            float2 v1 = make_float2(acc[mt][nt][2], acc[mt][nt][3]);
            *(float2*)&C[(size_t)row * ldc + col] = v0;
            *(float2*)&C[(size_t)(row + 8) * ldc + col] = v1;
        }
    }
}

// ---------------------------------------------------------------------------
// Kernel 2: scores + softmax + context, fused (R7 form, unchanged except
// kpT layout: rows d with ld = 8192, column base b*TH).
// grid = (TQ/4, B) = 512 blocks, 256 threads, 4 queries per block.
// ---------------------------------------------------------------------------
__global__ __launch_bounds__(256) void attn_kernel(
    const float* __restrict__ keys, const float* __restrict__ v,
    const float* __restrict__ qp_g, float* __restrict__ out)
{
    __shared__ __align__(16) float stage[2][16][260];
    __shared__ __align__(16) float sc[4][256];
    __shared__ __align__(16) float4 sqp4[256];
    __shared__ __align__(16) float sv[256];
    __shared__ float sinv[4];

    const int b    = blockIdx.y;
    const int q0   = blockIdx.x * 4;
    const int tid  = threadIdx.x;
    const int warp = tid >> 5;
    const int lane = tid & 31;

    sv[tid] = v[tid];
    {
        float4 p;
        p.x = qp_g[(size_t)(b * TQ + q0 + 0) * DD + tid];
        p.y = qp_g[(size_t)(b * TQ + q0 + 1) * DD + tid];
        p.z = qp_g[(size_t)(b * TQ + q0 + 2) * DD + tid];
        p.w = qp_g[(size_t)(b * TQ + q0 + 3) * DD + tid];
        sqp4[tid] = p;
    }

    const float* kpT = g_kpT + (size_t)b * TH;   // column offset; ld = NTOT
    const int r_  = tid >> 6;
    const int c4_ = (tid & 63) << 2;

    // ---- scores ----
    float acc[4] = {0.f, 0.f, 0.f, 0.f};
    float4 pf[4];

#pragma unroll
    for (int s = 0; s < 4; s++)
        pf[s] = *(const float4*)&kpT[(size_t)(r_ + s * 4) * NTOT + c4_];
#pragma unroll
    for (int s = 0; s < 4; s++) *(float4*)&stage[0][r_ + s * 4][c4_] = pf[s];
#pragma unroll
    for (int s = 0; s < 4; s++)
        pf[s] = *(const float4*)&kpT[(size_t)(16 + r_ + s * 4) * NTOT + c4_];
    __syncthreads();

    for (int c = 0; c < 16; c++) {
        const int cur = c & 1, nxt = cur ^ 1;
        if (c < 15) {
#pragma unroll
            for (int s = 0; s < 4; s++) *(float4*)&stage[nxt][r_ + s * 4][c4_] = pf[s];
            if (c < 14) {
                const int d0n = (c + 2) * 16;
#pragma unroll
                for (int s = 0; s < 4; s++)
                    pf[s] = *(const float4*)&kpT[(size_t)(d0n + r_ + s * 4) * NTOT + c4_];
            }
        }
        const int d0 = c * 16;
        float vr[16];
#pragma unroll
        for (int s = 0; s < 4; s++) {
            float4 vv = *(const float4*)&sv[d0 + s * 4];
            vr[s * 4 + 0] = vv.x; vr[s * 4 + 1] = vv.y;
            vr[s * 4 + 2] = vv.z; vr[s * 4 + 3] = vv.w;
        }
#pragma unroll
        for (int dd = 0; dd < 16; dd++) {
            float4 qv = sqp4[d0 + dd];
            float x  = stage[cur][dd][tid];
            acc[0] = fmaf(vr[dd], tanh_fast(qv.x + x), acc[0]);
            acc[1] = fmaf(vr[dd], tanh_fast(qv.y + x), acc[1]);
            acc[2] = fmaf(vr[dd], tanh_fast(qv.z + x), acc[2]);
            acc[3] = fmaf(vr[dd], tanh_fast(qv.w + x), acc[3]);
        }
        __syncthreads();
    }
#pragma unroll
    for (int q = 0; q < 4; q++) sc[q][tid] = acc[q];
    __syncthreads();

    // ---- softmax (unnormalized) ----
    if (warp < 4) {
        float ls[8];
        float m = -1e30f;
#pragma unroll
        for (int j = 0; j < 8; j++) {
            ls[j] = sc[warp][j * 32 + lane];
            m = fmaxf(m, ls[j]);
        }
#pragma unroll
        for (int o = 16; o; o >>= 1) m = fmaxf(m, __shfl_xor_sync(0xffffffffu, m, o));
        float ssum = 0.f;
#pragma unroll
        for (int j = 0; j < 8; j++) {
            ls[j] = __expf(ls[j] - m);
            ssum += ls[j];
        }
#pragma unroll
        for (int o = 16; o; o >>= 1) ssum += __shfl_xor_sync(0xffffffffu, ssum, o);
#pragma unroll
        for (int j = 0; j < 8; j++) sc[warp][j * 32 + lane] = ls[j];
        if (lane == 0) sinv[warp] = 1.f / ssum;
    }

    // ---- context ----
    float ctx[4] = {0.f, 0.f, 0.f, 0.f};
    const float* kb = keys + (size_t)b * TH * DIN;

#pragma unroll
    for (int s = 0; s < 4; s++)
        pf[s] = *(const float4*)&kb[(size_t)(r_ + s * 4) * DIN + c4_];
    __syncthreads();
#pragma unroll
    for (int s = 0; s < 4; s++) *(float4*)&stage[0][r_ + s * 4][c4_] = pf[s];
#pragma unroll
    for (int s = 0; s < 4; s++)
        pf[s] = *(const float4*)&kb[(size_t)(16 + r_ + s * 4) * DIN + c4_];
    __syncthreads();

    for (int c = 0; c < 16; c++) {
        const int cur = c & 1, nxt = cur ^ 1;
        if (c < 15) {
#pragma unroll
            for (int s = 0; s < 4; s++) *(float4*)&stage[nxt][r_ + s * 4][c4_] = pf[s];
            if (c < 14) {
                const int t0n = (c + 2) * 16;
#pragma unroll
                for (int s = 0; s < 4; s++)
                    pf[s] = *(const float4*)&kb[(size_t)(t0n + r_ + s * 4) * DIN + c4_];
            }
        }
        const int t0 = c * 16;
#pragma unroll
        for (int tg = 0; tg < 4; tg++) {
            float kv0 = stage[cur][tg * 4 + 0][tid];
            float kv1 = stage[cur][tg * 4 + 1][tid];
            float kv2 = stage[cur][tg * 4 + 2][tid];
            float kv3 = stage[cur][tg * 4 + 3][tid];
#pragma unroll
            for (int q = 0; q < 4; q++) {
                float4 a = *(const float4*)&sc[q][t0 + tg * 4];
                ctx[q] = fmaf(a.x, kv0,
                         fmaf(a.y, kv1,
                         fmaf(a.z, kv2,
                         fmaf(a.w, kv3, ctx[q]))));
            }
        }
        __syncthreads();
    }

#pragma unroll
    for (int q = 0; q < 4; q++)
        out[(size_t)(b * TQ + q0 + q) * DIN + tid] = ctx[q] * sinv[q];
}

// ---------------------------------------------------------------------------
// Launch. Inputs (metadata order): inputs, state, w1, w2, v, batch_size.
// Output: (B*TQ, DIN) float32.
// ---------------------------------------------------------------------------
extern "C" void kernel_launch(void* const* d_in, const int* in_sizes, int n_in,
                              void* d_out, int out_size)
{
    const float* inputs = (const float*)d_in[0];
    const float* state  = (const float*)d_in[1];
    const float* w1     = (const float*)d_in[2];
    const float* w2     = (const float*)d_in[3];
    const float* v      = (const float*)d_in[4];
    float* out = (float*)d_out;
    (void)in_sizes; (void)n_in; (void)out_size;

    proj_tc<<<160, 256>>>(inputs, state, w1, w2);

    float* qp_ptr;
    cudaGetSymbolAddress((void**)&qp_ptr, g_qp);

    dim3 g2(TQ / 4, B_);       // (16, 32) = 512 blocks, 4 queries each
    attn_kernel<<<g2, 256>>>(inputs, v, qp_ptr, out);
}

// round 10
// speedup vs baseline: 1.3482x; 1.3482x over previous
#include <cuda_runtime.h>
#include <cstdint>

// Problem constants
#define B_    32
#define TH    256
#define TQ    64
#define DIN   256
#define DD    256
#define KD    256
#define NTOT  (B_ * TH)   // 8192 global t

// Scratch (allocation-free rule: __device__ globals)
__device__ float g_kpT[B_ * DD * TH];  // 8 MB: [b][d][t], ld = 256
__device__ float g_qp [B_ * TQ * DD];  // 2 MB: [q_global][d]

__device__ __forceinline__ float tanh_fast(float x) {
    float y;
    asm("tanh.approx.f32 %0, %1;" : "=f"(y) : "f"(x));
    return y;
}

// ---- tf32 mma helpers ----
__device__ __forceinline__ unsigned f2tf(float f) {
    unsigned u; asm("cvt.rna.tf32.f32 %0, %1;" : "=r"(u) : "f"(f)); return u;
}
__device__ __forceinline__ void mma_tf32(
    float c[4], unsigned a0, unsigned a1, unsigned a2, unsigned a3,
    unsigned b0, unsigned b1)
{
    asm("mma.sync.aligned.m16n8k8.row.col.f32.tf32.tf32.f32 "
        "{%0,%1,%2,%3}, {%4,%5,%6,%7}, {%8,%9}, {%0,%1,%2,%3};"
        : "+f"(c[0]), "+f"(c[1]), "+f"(c[2]), "+f"(c[3])
        : "r"(a0), "r"(a1), "r"(a2), "r"(a3), "r"(b0), "r"(b1));
}

// ---------------------------------------------------------------------------
// Kernel 1: tensor-core (tf32) projection GEMMs.
//   GEMM1 (blocks 0..127):   kpT[b][d][t] = sum_k w1[d,k] * inputs[b*TH+t,k]
//       M=256 (d), N=8192 (n=b*TH+t). BN=128 divides TH -> each n-tile lies
//       in ONE batch b: store to [b][d][t] layout directly.
//   GEMM2 (blocks 128..159): g_qp[q][d] = sum_k state[q,k] * w2[d,k]
// Block tile 128x128, BK=16 double-buffered, 8 warps (4m x 2n), warp 32x64.
// __launch_bounds__(256,2): 2 CTAs/SM -> 160 blocks fit in ONE wave.
// ---------------------------------------------------------------------------
#define BM   128
#define BN   128
#define BK   16
#define SPAD 20   // floats per staged row: 80 B (16B-aligned), conflict-free

__global__ __launch_bounds__(256, 2) void proj_tc(
    const float* __restrict__ inputs, const float* __restrict__ state,
    const float* __restrict__ w1, const float* __restrict__ w2)
{
    __shared__ __align__(16) unsigned As[2][BM * SPAD];  // 20 KB
    __shared__ __align__(16) unsigned Bs[2][BN * SPAD];  // 20 KB

    const float* A;
    const float* Bsrc;
    int m0, n0;
    bool is_kp;
    int id = blockIdx.x;
    if (id < 128) {            // GEMM1: kpT
        is_kp = true;
        A = w1; Bsrc = inputs;
        m0 = (id & 1) * BM;    // 2 m-tiles (d)
        n0 = (id >> 1) * BN;   // 64 n-tiles (global t)
    } else {                   // GEMM2: qp
        is_kp = false;
        id -= 128;
        A = state; Bsrc = w2;
        m0 = (id & 15) * BM;   // 16 m-tiles (q)
        n0 = (id >> 4) * BN;   // 2 n-tiles (d)
    }

    const int tid  = threadIdx.x;
    const int warp = tid >> 5, lane = tid & 31;
    const int g    = lane >> 2, tig = lane & 3;
    const int wm   = (warp >> 1) * 32;   // warp m-offset
    const int wn   = (warp & 1) * 64;    // warp n-offset

    // staging: thread owns row srow = tid>>1, k-halves sk4 / sk4+4
    const int srow = tid >> 1;
    const int sk4  = (tid & 1) * 8;
    const float* pa = A    + (size_t)(m0 + srow) * KD + sk4;
    const float* pb = Bsrc + (size_t)(n0 + srow) * KD + sk4;

    float acc[2][8][4];
#pragma unroll
    for (int mt = 0; mt < 2; mt++)
#pragma unroll
        for (int nt = 0; nt < 8; nt++)
#pragma unroll
            for (int i = 0; i < 4; i++) acc[mt][nt][i] = 0.f;

    float4 fa0, fa1, fb0, fb1;

    // prologue: chunk 0 -> buf0, prefetch chunk 1
    fa0 = *(const float4*)&pa[0];  fa1 = *(const float4*)&pa[4];
    fb0 = *(const float4*)&pb[0];  fb1 = *(const float4*)&pb[4];
    {
        uint4 u;
        u.x = f2tf(fa0.x); u.y = f2tf(fa0.y); u.z = f2tf(fa0.z); u.w = f2tf(fa0.w);
        *(uint4*)&As[0][srow * SPAD + sk4] = u;
        u.x = f2tf(fa1.x); u.y = f2tf(fa1.y); u.z = f2tf(fa1.z); u.w = f2tf(fa1.w);
        *(uint4*)&As[0][srow * SPAD + sk4 + 4] = u;
        u.x = f2tf(fb0.x); u.y = f2tf(fb0.y); u.z = f2tf(fb0.z); u.w = f2tf(fb0.w);
        *(uint4*)&Bs[0][srow * SPAD + sk4] = u;
        u.x = f2tf(fb1.x); u.y = f2tf(fb1.y); u.z = f2tf(fb1.z); u.w = f2tf(fb1.w);
        *(uint4*)&Bs[0][srow * SPAD + sk4 + 4] = u;
    }
    fa0 = *(const float4*)&pa[BK];  fa1 = *(const float4*)&pa[BK + 4];
    fb0 = *(const float4*)&pb[BK];  fb1 = *(const float4*)&pb[BK + 4];
    __syncthreads();

    for (int c = 0; c < KD / BK; c++) {       // 16 chunks
        const int cur = c & 1, nxt = cur ^ 1;
        if (c < 15) {
            uint4 u;
            u.x = f2tf(fa0.x); u.y = f2tf(fa0.y); u.z = f2tf(fa0.z); u.w = f2tf(fa0.w);
            *(uint4*)&As[nxt][srow * SPAD + sk4] = u;
            u.x = f2tf(fa1.x); u.y = f2tf(fa1.y); u.z = f2tf(fa1.z); u.w = f2tf(fa1.w);
            *(uint4*)&As[nxt][srow * SPAD + sk4 + 4] = u;
            u.x = f2tf(fb0.x); u.y = f2tf(fb0.y); u.z = f2tf(fb0.z); u.w = f2tf(fb0.w);
            *(uint4*)&Bs[nxt][srow * SPAD + sk4] = u;
            u.x = f2tf(fb1.x); u.y = f2tf(fb1.y); u.z = f2tf(fb1.z); u.w = f2tf(fb1.w);
            *(uint4*)&Bs[nxt][srow * SPAD + sk4 + 4] = u;
            if (c < 14) {
                const int ko = (c + 2) * BK;
                fa0 = *(const float4*)&pa[ko];  fa1 = *(const float4*)&pa[ko + 4];
                fb0 = *(const float4*)&pb[ko];  fb1 = *(const float4*)&pb[ko + 4];
            }
        }
#pragma unroll
        for (int ks = 0; ks < 2; ks++) {      // two k=8 steps per chunk
            const int kb = ks * 8;
            unsigned a[2][4], b[8][2];
#pragma unroll
            for (int mt = 0; mt < 2; mt++) {
                const int r = wm + mt * 16 + g;
                a[mt][0] = As[cur][r * SPAD + kb + tig];
                a[mt][1] = As[cur][(r + 8) * SPAD + kb + tig];
                a[mt][2] = As[cur][r * SPAD + kb + tig + 4];
                a[mt][3] = As[cur][(r + 8) * SPAD + kb + tig + 4];
            }
#pragma unroll
            for (int nt = 0; nt < 8; nt++) {
                const int n = wn + nt * 8 + g;
                b[nt][0] = Bs[cur][n * SPAD + kb + tig];
                b[nt][1] = Bs[cur][n * SPAD + kb + tig + 4];
            }
#pragma unroll
            for (int mt = 0; mt < 2; mt++)
#pragma unroll
                for (int nt = 0; nt < 8; nt++)
                    mma_tf32(acc[mt][nt],
                             a[mt][0], a[mt][1], a[mt][2], a[mt][3],
                             b[nt][0], b[nt][1]);
        }
        __syncthreads();
    }

    // store C
    if (is_kp) {
        // [b][d][t] layout: the whole n-tile lies in batch bb
        const int bb = n0 >> 8;
        const int t0 = n0 & 255;
        float* C = g_kpT + (size_t)bb * DD * TH;
#pragma unroll
        for (int mt = 0; mt < 2; mt++) {
            const int row = m0 + wm + mt * 16 + g;
#pragma unroll
            for (int nt = 0; nt < 8; nt++) {
                const int col = t0 + wn + nt * 8 + 2 * tig;
                *(float2*)&C[(size_t)row * TH + col] =
                    make_float2(acc[mt][nt][0], acc[mt][nt][1]);
                *(float2*)&C[(size_t)(row + 8) * TH + col] =
                    make_float2(acc[mt][nt][2], acc[mt][nt][3]);
            }
        }
    } else {
#pragma unroll
        for (int mt = 0; mt < 2; mt++) {
            const int row = m0 + wm + mt * 16 + g;
#pragma unroll
            for (int nt = 0; nt < 8; nt++) {
                const int col = n0 + wn + nt * 8 + 2 * tig;
                *(float2*)&g_qp[(size_t)row * DD + col] =
                    make_float2(acc[mt][nt][0], acc[mt][nt][1]);
                *(float2*)&g_qp[(size_t)(row + 8) * DD + col] =
                    make_float2(acc[mt][nt][2], acc[mt][nt][3]);
            }
        }
    }
}

// ---------------------------------------------------------------------------
// Kernel 2: scores + softmax + context, fused (exact R8 form — 60.4 us).
// grid = (TQ/4, B) = 512 blocks, 256 threads, 4 queries per block.
// ---------------------------------------------------------------------------
__global__ __launch_bounds__(256) void attn_kernel(
    const float* __restrict__ keys, const float* __restrict__ v,
    const float* __restrict__ qp_g, float* __restrict__ out)
{
    __shared__ __align__(16) float stage[2][16][260];
    __shared__ __align__(16) float sc[4][256];
    __shared__ __align__(16) float4 sqp4[256];
    __shared__ __align__(16) float sv[256];
    __shared__ float sinv[4];

    const int b    = blockIdx.y;
    const int q0   = blockIdx.x * 4;
    const int tid  = threadIdx.x;
    const int warp = tid >> 5;
    const int lane = tid & 31;

    sv[tid] = v[tid];
    {
        float4 p;
        p.x = qp_g[(size_t)(b * TQ + q0 + 0) * DD + tid];
        p.y = qp_g[(size_t)(b * TQ + q0 + 1) * DD + tid];
        p.z = qp_g[(size_t)(b * TQ + q0 + 2) * DD + tid];
        p.w = qp_g[(size_t)(b * TQ + q0 + 3) * DD + tid];
        sqp4[tid] = p;
    }

    const float* kpT = g_kpT + (size_t)b * DD * TH;   // [d][t], ld = TH
    const int r_  = tid >> 6;
    const int c4_ = (tid & 63) << 2;

    // ---- scores: s[q][t] = sum_d v[d] * tanh(qp[q][d] + kp[d][t]) ----
    float acc[4] = {0.f, 0.f, 0.f, 0.f};
    float4 pf[4];

#pragma unroll
    for (int s = 0; s < 4; s++)
        pf[s] = *(const float4*)&kpT[(size_t)(r_ + s * 4) * TH + c4_];
#pragma unroll
    for (int s = 0; s < 4; s++) *(float4*)&stage[0][r_ + s * 4][c4_] = pf[s];
#pragma unroll
    for (int s = 0; s < 4; s++)
        pf[s] = *(const float4*)&kpT[(size_t)(16 + r_ + s * 4) * TH + c4_];
    __syncthreads();

    for (int c = 0; c < 16; c++) {
        const int cur = c & 1, nxt = cur ^ 1;
        if (c < 15) {
#pragma unroll
            for (int s = 0; s < 4; s++) *(float4*)&stage[nxt][r_ + s * 4][c4_] = pf[s];
            if (c < 14) {
                const int d0n = (c + 2) * 16;
#pragma unroll
                for (int s = 0; s < 4; s++)
                    pf[s] = *(const float4*)&kpT[(size_t)(d0n + r_ + s * 4) * TH + c4_];
            }
        }
        const int d0 = c * 16;
        float vr[16];
#pragma unroll
        for (int s = 0; s < 4; s++) {
            float4 vv = *(const float4*)&sv[d0 + s * 4];
            vr[s * 4 + 0] = vv.x; vr[s * 4 + 1] = vv.y;
            vr[s * 4 + 2] = vv.z; vr[s * 4 + 3] = vv.w;
        }
#pragma unroll
        for (int dd = 0; dd < 16; dd++) {
            float4 qv = sqp4[d0 + dd];
            float x  = stage[cur][dd][tid];
            acc[0] = fmaf(vr[dd], tanh_fast(qv.x + x), acc[0]);
            acc[1] = fmaf(vr[dd], tanh_fast(qv.y + x), acc[1]);
            acc[2] = fmaf(vr[dd], tanh_fast(qv.z + x), acc[2]);
            acc[3] = fmaf(vr[dd], tanh_fast(qv.w + x), acc[3]);
        }
        __syncthreads();
    }
#pragma unroll
    for (int q = 0; q < 4; q++) sc[q][tid] = acc[q];
    __syncthreads();

    // ---- softmax (unnormalized): warps 0-3, one query each ----
    if (warp < 4) {
        float ls[8];
        float m = -1e30f;
#pragma unroll
        for (int j = 0; j < 8; j++) {
            ls[j] = sc[warp][j * 32 + lane];
            m = fmaxf(m, ls[j]);
        }
#pragma unroll
        for (int o = 16; o; o >>= 1) m = fmaxf(m, __shfl_xor_sync(0xffffffffu, m, o));
        float ssum = 0.f;
#pragma unroll
        for (int j = 0; j < 8; j++) {
            ls[j] = __expf(ls[j] - m);
            ssum += ls[j];
        }
#pragma unroll
        for (int o = 16; o; o >>= 1) ssum += __shfl_xor_sync(0xffffffffu, ssum, o);
#pragma unroll
        for (int j = 0; j < 8; j++) sc[warp][j * 32 + lane] = ls[j];
        if (lane == 0) sinv[warp] = 1.f / ssum;
    }

    // ---- context[i] = (1/sum) * sum_t e[t] * keys[b][t][i]; i = tid ----
    float ctx[4] = {0.f, 0.f, 0.f, 0.f};
    const float* kb = keys + (size_t)b * TH * DIN;

#pragma unroll
    for (int s = 0; s < 4; s++)
        pf[s] = *(const float4*)&kb[(size_t)(r_ + s * 4) * DIN + c4_];
    __syncthreads();
#pragma unroll
    for (int s = 0; s < 4; s++) *(float4*)&stage[0][r_ + s * 4][c4_] = pf[s];
#pragma unroll
    for (int s = 0; s < 4; s++)
        pf[s] = *(const float4*)&kb[(size_t)(16 + r_ + s * 4) * DIN + c4_];
    __syncthreads();

    for (int c = 0; c < 16; c++) {
        const int cur = c & 1, nxt = cur ^ 1;
        if (c < 15) {
#pragma unroll
            for (int s = 0; s < 4; s++) *(float4*)&stage[nxt][r_ + s * 4][c4_] = pf[s];
            if (c < 14) {
                const int t0n = (c + 2) * 16;
#pragma unroll
                for (int s = 0; s < 4; s++)
                    pf[s] = *(const float4*)&kb[(size_t)(t0n + r_ + s * 4) * DIN + c4_];
            }
        }
        const int t0 = c * 16;
#pragma unroll
        for (int tg = 0; tg < 4; tg++) {
            float kv0 = stage[cur][tg * 4 + 0][tid];
            float kv1 = stage[cur][tg * 4 + 1][tid];
            float kv2 = stage[cur][tg * 4 + 2][tid];
            float kv3 = stage[cur][tg * 4 + 3][tid];
#pragma unroll
            for (int q = 0; q < 4; q++) {
                float4 a = *(const float4*)&sc[q][t0 + tg * 4];
                ctx[q] = fmaf(a.x, kv0,
                         fmaf(a.y, kv1,
                         fmaf(a.z, kv2,
                         fmaf(a.w, kv3, ctx[q]))));
            }
        }
        __syncthreads();
    }

#pragma unroll
    for (int q = 0; q < 4; q++)
        out[(size_t)(b * TQ + q0 + q) * DIN + tid] = ctx[q] * sinv[q];
}

// ---------------------------------------------------------------------------
// Launch. Inputs (metadata order): inputs, state, w1, w2, v, batch_size.
// Output: (B*TQ, DIN) float32.
// ---------------------------------------------------------------------------
extern "C" void kernel_launch(void* const* d_in, const int* in_sizes, int n_in,
                              void* d_out, int out_size)
{
    const float* inputs = (const float*)d_in[0];
    const float* state  = (const float*)d_in[1];
    const float* w1     = (const float*)d_in[2];
    const float* w2     = (const float*)d_in[3];
    const float* v      = (const float*)d_in[4];
    float* out = (float*)d_out;
    (void)in_sizes; (void)n_in; (void)out_size;

    proj_tc<<<160, 256>>>(inputs, state, w1, w2);

    float* qp_ptr;
    cudaGetSymbolAddress((void**)&qp_ptr, g_qp);

    dim3 g2(TQ / 4, B_);       // (16, 32) = 512 blocks, 4 queries each
    attn_kernel<<<g2, 256>>>(inputs, v, qp_ptr, out);
}

// round 12
// speedup vs baseline: 1.3516x; 1.0025x over previous
#include <cuda_runtime.h>
#include <cuda_fp16.h>
#include <cstdint>

// Problem constants
#define B_    32
#define TH    256
#define TQ    64
#define DIN   256
#define DD    256
#define KD    256
#define NTOT  (B_ * TH)   // 8192 global t

// Scratch (allocation-free rule: __device__ globals)
__device__ float g_kpT[B_ * DD * TH];  // 8 MB: [b][d][t], ld = 256
__device__ float g_qp [B_ * TQ * DD];  // 2 MB: [q_global][d]

// ---- f16x2 MUFU tanh (2 tanh per MUFU op); renamed to avoid cuda_fp16.hpp ----
__device__ __forceinline__ __half2 tanh_f16x2(__half2 x) {
    unsigned xu = *(unsigned*)&x;
    unsigned ru;
    asm("tanh.approx.f16x2 %0, %1;" : "=r"(ru) : "r"(xu));
    return *(__half2*)&ru;
}

// ---- tf32 mma helpers ----
__device__ __forceinline__ unsigned f2tf(float f) {
    unsigned u; asm("cvt.rna.tf32.f32 %0, %1;" : "=r"(u) : "f"(f)); return u;
}
__device__ __forceinline__ void mma_tf32(
    float c[4], unsigned a0, unsigned a1, unsigned a2, unsigned a3,
    unsigned b0, unsigned b1)
{
    asm("mma.sync.aligned.m16n8k8.row.col.f32.tf32.tf32.f32 "
        "{%0,%1,%2,%3}, {%4,%5,%6,%7}, {%8,%9}, {%0,%1,%2,%3};"
        : "+f"(c[0]), "+f"(c[1]), "+f"(c[2]), "+f"(c[3])
        : "r"(a0), "r"(a1), "r"(a2), "r"(a3), "r"(b0), "r"(b1));
}

// ---------------------------------------------------------------------------
// Kernel 1: tensor-core (tf32) projection GEMMs (R9 form, unchanged).
// ---------------------------------------------------------------------------
#define BM   128
#define BN   128
#define BK   16
#define SPAD 20

__global__ __launch_bounds__(256, 2) void proj_tc(
    const float* __restrict__ inputs, const float* __restrict__ state,
    const float* __restrict__ w1, const float* __restrict__ w2)
{
    __shared__ __align__(16) unsigned As[2][BM * SPAD];
    __shared__ __align__(16) unsigned Bs[2][BN * SPAD];

    const float* A;
    const float* Bsrc;
    int m0, n0;
    bool is_kp;
    int id = blockIdx.x;
    if (id < 128) {            // GEMM1: kpT
        is_kp = true;
        A = w1; Bsrc = inputs;
        m0 = (id & 1) * BM;
        n0 = (id >> 1) * BN;
    } else {                   // GEMM2: qp
        is_kp = false;
        id -= 128;
        A = state; Bsrc = w2;
        m0 = (id & 15) * BM;
        n0 = (id >> 4) * BN;
    }

    const int tid  = threadIdx.x;
    const int warp = tid >> 5, lane = tid & 31;
    const int g    = lane >> 2, tig = lane & 3;
    const int wm   = (warp >> 1) * 32;
    const int wn   = (warp & 1) * 64;

    const int srow = tid >> 1;
    const int sk4  = (tid & 1) * 8;
    const float* pa = A    + (size_t)(m0 + srow) * KD + sk4;
    const float* pb = Bsrc + (size_t)(n0 + srow) * KD + sk4;

    float acc[2][8][4];
#pragma unroll
    for (int mt = 0; mt < 2; mt++)
#pragma unroll
        for (int nt = 0; nt < 8; nt++)
#pragma unroll
            for (int i = 0; i < 4; i++) acc[mt][nt][i] = 0.f;

    float4 fa0, fa1, fb0, fb1;

    fa0 = *(const float4*)&pa[0];  fa1 = *(const float4*)&pa[4];
    fb0 = *(const float4*)&pb[0];  fb1 = *(const float4*)&pb[4];
    {
        uint4 u;
        u.x = f2tf(fa0.x); u.y = f2tf(fa0.y); u.z = f2tf(fa0.z); u.w = f2tf(fa0.w);
        *(uint4*)&As[0][srow * SPAD + sk4] = u;
        u.x = f2tf(fa1.x); u.y = f2tf(fa1.y); u.z = f2tf(fa1.z); u.w = f2tf(fa1.w);
        *(uint4*)&As[0][srow * SPAD + sk4 + 4] = u;
        u.x = f2tf(fb0.x); u.y = f2tf(fb0.y); u.z = f2tf(fb0.z); u.w = f2tf(fb0.w);
        *(uint4*)&Bs[0][srow * SPAD + sk4] = u;
        u.x = f2tf(fb1.x); u.y = f2tf(fb1.y); u.z = f2tf(fb1.z); u.w = f2tf(fb1.w);
        *(uint4*)&Bs[0][srow * SPAD + sk4 + 4] = u;
    }
    fa0 = *(const float4*)&pa[BK];  fa1 = *(const float4*)&pa[BK + 4];
    fb0 = *(const float4*)&pb[BK];  fb1 = *(const float4*)&pb[BK + 4];
    __syncthreads();

    for (int c = 0; c < KD / BK; c++) {
        const int cur = c & 1, nxt = cur ^ 1;
        if (c < 15) {
            uint4 u;
            u.x = f2tf(fa0.x); u.y = f2tf(fa0.y); u.z = f2tf(fa0.z); u.w = f2tf(fa0.w);
            *(uint4*)&As[nxt][srow * SPAD + sk4] = u;
            u.x = f2tf(fa1.x); u.y = f2tf(fa1.y); u.z = f2tf(fa1.z); u.w = f2tf(fa1.w);
            *(uint4*)&As[nxt][srow * SPAD + sk4 + 4] = u;
            u.x = f2tf(fb0.x); u.y = f2tf(fb0.y); u.z = f2tf(fb0.z); u.w = f2tf(fb0.w);
            *(uint4*)&Bs[nxt][srow * SPAD + sk4] = u;
            u.x = f2tf(fb1.x); u.y = f2tf(fb1.y); u.z = f2tf(fb1.z); u.w = f2tf(fb1.w);
            *(uint4*)&Bs[nxt][srow * SPAD + sk4 + 4] = u;
            if (c < 14) {
                const int ko = (c + 2) * BK;
                fa0 = *(const float4*)&pa[ko];  fa1 = *(const float4*)&pa[ko + 4];
                fb0 = *(const float4*)&pb[ko];  fb1 = *(const float4*)&pb[ko + 4];
            }
        }
#pragma unroll
        for (int ks = 0; ks < 2; ks++) {
            const int kb = ks * 8;
            unsigned a[2][4], b[8][2];
#pragma unroll
            for (int mt = 0; mt < 2; mt++) {
                const int r = wm + mt * 16 + g;
                a[mt][0] = As[cur][r * SPAD + kb + tig];
                a[mt][1] = As[cur][(r + 8) * SPAD + kb + tig];
                a[mt][2] = As[cur][r * SPAD + kb + tig + 4];
                a[mt][3] = As[cur][(r + 8) * SPAD + kb + tig + 4];
            }
#pragma unroll
            for (int nt = 0; nt < 8; nt++) {
                const int n = wn + nt * 8 + g;
                b[nt][0] = Bs[cur][n * SPAD + kb + tig];
                b[nt][1] = Bs[cur][n * SPAD + kb + tig + 4];
            }
#pragma unroll
            for (int mt = 0; mt < 2; mt++)
#pragma unroll
                for (int nt = 0; nt < 8; nt++)
                    mma_tf32(acc[mt][nt],
                             a[mt][0], a[mt][1], a[mt][2], a[mt][3],
                             b[nt][0], b[nt][1]);
        }
        __syncthreads();
    }

    if (is_kp) {
        const int bb = n0 >> 8;
        const int t0 = n0 & 255;
        float* C = g_kpT + (size_t)bb * DD * TH;
#pragma unroll
        for (int mt = 0; mt < 2; mt++) {
            const int row = m0 + wm + mt * 16 + g;
#pragma unroll
            for (int nt = 0; nt < 8; nt++) {
                const int col = t0 + wn + nt * 8 + 2 * tig;
                *(float2*)&C[(size_t)row * TH + col] =
                    make_float2(acc[mt][nt][0], acc[mt][nt][1]);
                *(float2*)&C[(size_t)(row + 8) * TH + col] =
                    make_float2(acc[mt][nt][2], acc[mt][nt][3]);
            }
        }
    } else {
#pragma unroll
        for (int mt = 0; mt < 2; mt++) {
            const int row = m0 + wm + mt * 16 + g;
#pragma unroll
            for (int nt = 0; nt < 8; nt++) {
                const int col = n0 + wn + nt * 8 + 2 * tig;
                *(float2*)&g_qp[(size_t)row * DD + col] =
                    make_float2(acc[mt][nt][0], acc[mt][nt][1]);
                *(float2*)&g_qp[(size_t)(row + 8) * DD + col] =
                    make_float2(acc[mt][nt][2], acc[mt][nt][3]);
            }
        }
    }
}

// ---------------------------------------------------------------------------
// Kernel 2: scores + softmax + context. Score phase uses tanh.approx.f16x2
// (2 tanh per MUFU op), f32 adds + f32 accumulation.
// grid = (TQ/4, B) = 512 blocks, 256 threads, 4 queries per block.
// ---------------------------------------------------------------------------
__global__ __launch_bounds__(256) void attn_kernel(
    const float* __restrict__ keys, const float* __restrict__ v,
    const float* __restrict__ qp_g, float* __restrict__ out)
{
    __shared__ __align__(16) float stage[2][16][260];
    __shared__ __align__(16) float sc[4][256];
    __shared__ __align__(16) float4 sqp4[256];
    __shared__ __align__(16) float sv[256];
    __shared__ float sinv[4];

    const int b    = blockIdx.y;
    const int q0   = blockIdx.x * 4;
    const int tid  = threadIdx.x;
    const int warp = tid >> 5;
    const int lane = tid & 31;

    sv[tid] = v[tid];
    {
        float4 p;
        p.x = qp_g[(size_t)(b * TQ + q0 + 0) * DD + tid];
        p.y = qp_g[(size_t)(b * TQ + q0 + 1) * DD + tid];
        p.z = qp_g[(size_t)(b * TQ + q0 + 2) * DD + tid];
        p.w = qp_g[(size_t)(b * TQ + q0 + 3) * DD + tid];
        sqp4[tid] = p;
    }

    const float* kpT = g_kpT + (size_t)b * DD * TH;   // [d][t], ld = TH
    const int r_  = tid >> 6;
    const int c4_ = (tid & 63) << 2;

    // ---- scores: s[q][t] = sum_d v[d] * tanh(qp[q][d] + kp[d][t]) ----
    float acc[4] = {0.f, 0.f, 0.f, 0.f};
    float4 pf[4];

#pragma unroll
    for (int s = 0; s < 4; s++)
        pf[s] = *(const float4*)&kpT[(size_t)(r_ + s * 4) * TH + c4_];
#pragma unroll
    for (int s = 0; s < 4; s++) *(float4*)&stage[0][r_ + s * 4][c4_] = pf[s];
#pragma unroll
    for (int s = 0; s < 4; s++)
        pf[s] = *(const float4*)&kpT[(size_t)(16 + r_ + s * 4) * TH + c4_];
    __syncthreads();

    for (int c = 0; c < 16; c++) {
        const int cur = c & 1, nxt = cur ^ 1;
        if (c < 15) {
#pragma unroll
            for (int s = 0; s < 4; s++) *(float4*)&stage[nxt][r_ + s * 4][c4_] = pf[s];
            if (c < 14) {
                const int d0n = (c + 2) * 16;
#pragma unroll
                for (int s = 0; s < 4; s++)
                    pf[s] = *(const float4*)&kpT[(size_t)(d0n + r_ + s * 4) * TH + c4_];
            }
        }
        const int d0 = c * 16;
        float vr[16];
#pragma unroll
        for (int s = 0; s < 4; s++) {
            float4 vv = *(const float4*)&sv[d0 + s * 4];
            vr[s * 4 + 0] = vv.x; vr[s * 4 + 1] = vv.y;
            vr[s * 4 + 2] = vv.z; vr[s * 4 + 3] = vv.w;
        }
#pragma unroll
        for (int dd = 0; dd < 16; dd++) {
            float4 qv = sqp4[d0 + dd];        // LDS.128 broadcast
            float x  = stage[cur][dd][tid];   // conflict-free
            // f32 adds (exact), pack to f16x2, 2-wide MUFU tanh, unpack, f32 FMA
            __half2 ha = __floats2half2_rn(qv.x + x, qv.y + x);
            __half2 hb = __floats2half2_rn(qv.z + x, qv.w + x);
            ha = tanh_f16x2(ha);
            hb = tanh_f16x2(hb);
            float2 fa = __half22float2(ha);
            float2 fb = __half22float2(hb);
            acc[0] = fmaf(vr[dd], fa.x, acc[0]);
            acc[1] = fmaf(vr[dd], fa.y, acc[1]);
            acc[2] = fmaf(vr[dd], fb.x, acc[2]);
            acc[3] = fmaf(vr[dd], fb.y, acc[3]);
        }
        __syncthreads();
    }
#pragma unroll
    for (int q = 0; q < 4; q++) sc[q][tid] = acc[q];
    __syncthreads();

    // ---- softmax (unnormalized): warps 0-3, one query each ----
    if (warp < 4) {
        float ls[8];
        float m = -1e30f;
#pragma unroll
        for (int j = 0; j < 8; j++) {
            ls[j] = sc[warp][j * 32 + lane];
            m = fmaxf(m, ls[j]);
        }
#pragma unroll
        for (int o = 16; o; o >>= 1) m = fmaxf(m, __shfl_xor_sync(0xffffffffu, m, o));
        float ssum = 0.f;
#pragma unroll
        for (int j = 0; j < 8; j++) {
            ls[j] = __expf(ls[j] - m);
            ssum += ls[j];
        }
#pragma unroll
        for (int o = 16; o; o >>= 1) ssum += __shfl_xor_sync(0xffffffffu, ssum, o);
#pragma unroll
        for (int j = 0; j < 8; j++) sc[warp][j * 32 + lane] = ls[j];
        if (lane == 0) sinv[warp] = 1.f / ssum;
    }

    // ---- context[i] = (1/sum) * sum_t e[t] * keys[b][t][i]; i = tid ----
    float ctx[4] = {0.f, 0.f, 0.f, 0.f};
    const float* kb = keys + (size_t)b * TH * DIN;

#pragma unroll
    for (int s = 0; s < 4; s++)
        pf[s] = *(const float4*)&kb[(size_t)(r_ + s * 4) * DIN + c4_];
    __syncthreads();
#pragma unroll
    for (int s = 0; s < 4; s++) *(float4*)&stage[0][r_ + s * 4][c4_] = pf[s];
#pragma unroll
    for (int s = 0; s < 4; s++)
        pf[s] = *(const float4*)&kb[(size_t)(16 + r_ + s * 4) * DIN + c4_];
    __syncthreads();

    for (int c = 0; c < 16; c++) {
        const int cur = c & 1, nxt = cur ^ 1;
        if (c < 15) {
#pragma unroll
            for (int s = 0; s < 4; s++) *(float4*)&stage[nxt][r_ + s * 4][c4_] = pf[s];
            if (c < 14) {
                const int t0n = (c + 2) * 16;
#pragma unroll
                for (int s = 0; s < 4; s++)
                    pf[s] = *(const float4*)&kb[(size_t)(t0n + r_ + s * 4) * DIN + c4_];
            }
        }
        const int t0 = c * 16;
#pragma unroll
        for (int tg = 0; tg < 4; tg++) {
            float kv0 = stage[cur][tg * 4 + 0][tid];
            float kv1 = stage[cur][tg * 4 + 1][tid];
            float kv2 = stage[cur][tg * 4 + 2][tid];
            float kv3 = stage[cur][tg * 4 + 3][tid];
#pragma unroll
            for (int q = 0; q < 4; q++) {
                float4 a = *(const float4*)&sc[q][t0 + tg * 4];
                ctx[q] = fmaf(a.x, kv0,
                         fmaf(a.y, kv1,
                         fmaf(a.z, kv2,
                         fmaf(a.w, kv3, ctx[q]))));
            }
        }
        __syncthreads();
    }

#pragma unroll
    for (int q = 0; q < 4; q++)
        out[(size_t)(b * TQ + q0 + q) * DIN + tid] = ctx[q] * sinv[q];
}

// ---------------------------------------------------------------------------
// Launch. Inputs (metadata order): inputs, state, w1, w2, v, batch_size.
// Output: (B*TQ, DIN) float32.
// ---------------------------------------------------------------------------
extern "C" void kernel_launch(void* const* d_in, const int* in_sizes, int n_in,
                              void* d_out, int out_size)
{
    const float* inputs = (const float*)d_in[0];
    const float* state  = (const float*)d_in[1];
    const float* w1     = (const float*)d_in[2];
    const float* w2     = (const float*)d_in[3];
    const float* v      = (const float*)d_in[4];
    float* out = (float*)d_out;
    (void)in_sizes; (void)n_in; (void)out_size;

    proj_tc<<<160, 256>>>(inputs, state, w1, w2);

    float* qp_ptr;
    cudaGetSymbolAddress((void**)&qp_ptr, g_qp);

    dim3 g2(TQ / 4, B_);       // (16, 32) = 512 blocks, 4 queries each
    attn_kernel<<<g2, 256>>>(inputs, v, qp_ptr, out);
}

// round 13
// speedup vs baseline: 1.4418x; 1.0667x over previous
#include <cuda_runtime.h>
#include <cuda_fp16.h>
#include <cstdint>

// Problem constants
#define B_    32
#define TH    256
#define TQ    64
#define DIN   256
#define DD    256
#define KD    256

// Scratch (allocation-free rule: __device__ globals)
__device__ __half g_kph  [B_ * DD * TH];   // 4 MB: [b][d][t] f16
__device__ __half g_qph  [B_ * TQ * DD];   // 1 MB: [q_global][d] f16
__device__ __half g_keysh[B_ * TH * DIN];  // 4 MB: [b][t][i] f16

// ---- f16x2 MUFU tanh (renamed: cuda_fp16.hpp owns h2tanh) ----
__device__ __forceinline__ __half2 tanh_f16x2(__half2 x) {
    unsigned xu = *(unsigned*)&x;
    unsigned ru;
    asm("tanh.approx.f16x2 %0, %1;" : "=r"(ru) : "r"(xu));
    return *(__half2*)&ru;
}

// ---- tf32 mma helpers ----
__device__ __forceinline__ unsigned f2tf(float f) {
    unsigned u; asm("cvt.rna.tf32.f32 %0, %1;" : "=r"(u) : "f"(f)); return u;
}
__device__ __forceinline__ void mma_tf32(
    float c[4], unsigned a0, unsigned a1, unsigned a2, unsigned a3,
    unsigned b0, unsigned b1)
{
    asm("mma.sync.aligned.m16n8k8.row.col.f32.tf32.tf32.f32 "
        "{%0,%1,%2,%3}, {%4,%5,%6,%7}, {%8,%9}, {%0,%1,%2,%3};"
        : "+f"(c[0]), "+f"(c[1]), "+f"(c[2]), "+f"(c[3])
        : "r"(a0), "r"(a1), "r"(a2), "r"(a3), "r"(b0), "r"(b1));
}

// ---------------------------------------------------------------------------
// Kernel 1: tf32 projection GEMMs, f16 outputs + keys f16 conversion riders.
//   blocks 0..127:   kph[b][d][t] = w1 @ inputs^T   (f16 store)
//   blocks 128..159: qph[q][d]    = state @ w2^T    (f16 store)
//   blocks 160..191: g_keysh[b] = f16(inputs[b])    (conversion riders)
// ---------------------------------------------------------------------------
#define BM   128
#define BN   128
#define BK   16
#define SPAD 20

__global__ __launch_bounds__(256, 2) void proj_tc(
    const float* __restrict__ inputs, const float* __restrict__ state,
    const float* __restrict__ w1, const float* __restrict__ w2)
{
    int id = blockIdx.x;

    if (id >= 160) {                  // keys f16 conversion riders
        const int bb = id - 160;
        const float4* src = (const float4*)(inputs + (size_t)bb * TH * DIN);
        __half2* dst = (__half2*)(g_keysh + (size_t)bb * TH * DIN);
        for (int i = threadIdx.x; i < TH * DIN / 4; i += 256) {
            float4 vv = src[i];
            dst[2 * i + 0] = __floats2half2_rn(vv.x, vv.y);
            dst[2 * i + 1] = __floats2half2_rn(vv.z, vv.w);
        }
        return;
    }

    __shared__ __align__(16) unsigned As[2][BM * SPAD];
    __shared__ __align__(16) unsigned Bs[2][BN * SPAD];

    const float* A;
    const float* Bsrc;
    int m0, n0;
    bool is_kp;
    if (id < 128) {            // GEMM1: kph
        is_kp = true;
        A = w1; Bsrc = inputs;
        m0 = (id & 1) * BM;
        n0 = (id >> 1) * BN;
    } else {                   // GEMM2: qph
        is_kp = false;
        id -= 128;
        A = state; Bsrc = w2;
        m0 = (id & 15) * BM;
        n0 = (id >> 4) * BN;
    }

    const int tid  = threadIdx.x;
    const int warp = tid >> 5, lane = tid & 31;
    const int g    = lane >> 2, tig = lane & 3;
    const int wm   = (warp >> 1) * 32;
    const int wn   = (warp & 1) * 64;

    const int srow = tid >> 1;
    const int sk4  = (tid & 1) * 8;
    const float* pa = A    + (size_t)(m0 + srow) * KD + sk4;
    const float* pb = Bsrc + (size_t)(n0 + srow) * KD + sk4;

    float acc[2][8][4];
#pragma unroll
    for (int mt = 0; mt < 2; mt++)
#pragma unroll
        for (int nt = 0; nt < 8; nt++)
#pragma unroll
            for (int i = 0; i < 4; i++) acc[mt][nt][i] = 0.f;

    float4 fa0, fa1, fb0, fb1;

    fa0 = *(const float4*)&pa[0];  fa1 = *(const float4*)&pa[4];
    fb0 = *(const float4*)&pb[0];  fb1 = *(const float4*)&pb[4];
    {
        uint4 u;
        u.x = f2tf(fa0.x); u.y = f2tf(fa0.y); u.z = f2tf(fa0.z); u.w = f2tf(fa0.w);
        *(uint4*)&As[0][srow * SPAD + sk4] = u;
        u.x = f2tf(fa1.x); u.y = f2tf(fa1.y); u.z = f2tf(fa1.z); u.w = f2tf(fa1.w);
        *(uint4*)&As[0][srow * SPAD + sk4 + 4] = u;
        u.x = f2tf(fb0.x); u.y = f2tf(fb0.y); u.z = f2tf(fb0.z); u.w = f2tf(fb0.w);
        *(uint4*)&Bs[0][srow * SPAD + sk4] = u;
        u.x = f2tf(fb1.x); u.y = f2tf(fb1.y); u.z = f2tf(fb1.z); u.w = f2tf(fb1.w);
        *(uint4*)&Bs[0][srow * SPAD + sk4 + 4] = u;
    }
    fa0 = *(const float4*)&pa[BK];  fa1 = *(const float4*)&pa[BK + 4];
    fb0 = *(const float4*)&pb[BK];  fb1 = *(const float4*)&pb[BK + 4];
    __syncthreads();

    for (int c = 0; c < KD / BK; c++) {
        const int cur = c & 1, nxt = cur ^ 1;
        if (c < 15) {
            uint4 u;
            u.x = f2tf(fa0.x); u.y = f2tf(fa0.y); u.z = f2tf(fa0.z); u.w = f2tf(fa0.w);
            *(uint4*)&As[nxt][srow * SPAD + sk4] = u;
            u.x = f2tf(fa1.x); u.y = f2tf(fa1.y); u.z = f2tf(fa1.z); u.w = f2tf(fa1.w);
            *(uint4*)&As[nxt][srow * SPAD + sk4 + 4] = u;
            u.x = f2tf(fb0.x); u.y = f2tf(fb0.y); u.z = f2tf(fb0.z); u.w = f2tf(fb0.w);
            *(uint4*)&Bs[nxt][srow * SPAD + sk4] = u;
            u.x = f2tf(fb1.x); u.y = f2tf(fb1.y); u.z = f2tf(fb1.z); u.w = f2tf(fb1.w);
            *(uint4*)&Bs[nxt][srow * SPAD + sk4 + 4] = u;
            if (c < 14) {
                const int ko = (c + 2) * BK;
                fa0 = *(const float4*)&pa[ko];  fa1 = *(const float4*)&pa[ko + 4];
                fb0 = *(const float4*)&pb[ko];  fb1 = *(const float4*)&pb[ko + 4];
            }
        }
#pragma unroll
        for (int ks = 0; ks < 2; ks++) {
            const int kb = ks * 8;
            unsigned a[2][4], b[8][2];
#pragma unroll
            for (int mt = 0; mt < 2; mt++) {
                const int r = wm + mt * 16 + g;
                a[mt][0] = As[cur][r * SPAD + kb + tig];
                a[mt][1] = As[cur][(r + 8) * SPAD + kb + tig];
                a[mt][2] = As[cur][r * SPAD + kb + tig + 4];
                a[mt][3] = As[cur][(r + 8) * SPAD + kb + tig + 4];
            }
#pragma unroll
            for (int nt = 0; nt < 8; nt++) {
                const int n = wn + nt * 8 + g;
                b[nt][0] = Bs[cur][n * SPAD + kb + tig];
                b[nt][1] = Bs[cur][n * SPAD + kb + tig + 4];
            }
#pragma unroll
            for (int mt = 0; mt < 2; mt++)
#pragma unroll
                for (int nt = 0; nt < 8; nt++)
                    mma_tf32(acc[mt][nt],
                             a[mt][0], a[mt][1], a[mt][2], a[mt][3],
                             b[nt][0], b[nt][1]);
        }
        __syncthreads();
    }

    if (is_kp) {
        const int bb = n0 >> 8;
        const int t0 = n0 & 255;
        __half* C = g_kph + (size_t)bb * DD * TH;
#pragma unroll
        for (int mt = 0; mt < 2; mt++) {
            const int row = m0 + wm + mt * 16 + g;
#pragma unroll
            for (int nt = 0; nt < 8; nt++) {
                const int col = t0 + wn + nt * 8 + 2 * tig;
                *(__half2*)&C[(size_t)row * TH + col] =
                    __floats2half2_rn(acc[mt][nt][0], acc[mt][nt][1]);
                *(__half2*)&C[(size_t)(row + 8) * TH + col] =
                    __floats2half2_rn(acc[mt][nt][2], acc[mt][nt][3]);
            }
        }
    } else {
#pragma unroll
        for (int mt = 0; mt < 2; mt++) {
            const int row = m0 + wm + mt * 16 + g;
#pragma unroll
            for (int nt = 0; nt < 8; nt++) {
                const int col = n0 + wn + nt * 8 + 2 * tig;
                *(__half2*)&g_qph[(size_t)row * DD + col] =
                    __floats2half2_rn(acc[mt][nt][0], acc[mt][nt][1]);
                *(__half2*)&g_qph[(size_t)(row + 8) * DD + col] =
                    __floats2half2_rn(acc[mt][nt][2], acc[mt][nt][3]);
            }
        }
    }
}

// ---------------------------------------------------------------------------
// Kernel 2: scores + softmax + context. grid (TQ/2, B) = 1024 blocks, 256
// threads, 2 queries/block. f16 staging (kp + keys), f16x2 HADD+tanh, f32
// accumulation. Double-buffered, 1 barrier per chunk.
// ---------------------------------------------------------------------------
#define HPAD 264   // halves per staged row (33 uint4)

__global__ __launch_bounds__(256) void attn_kernel(
    const float* __restrict__ v, float* __restrict__ out)
{
    __shared__ __align__(16) __half stage[2][16][HPAD];  // 16.9 KB
    __shared__ __align__(16) float sc[2][256];           // exp(scores)
    __shared__ __align__(16) __half2 sqh[256];           // {q0,q1} per d
    __shared__ __align__(16) float sv[256];              // v (f32, exact)
    __shared__ float sinv[2];

    const int b    = blockIdx.y;
    const int q0   = blockIdx.x * 2;
    const int tid  = threadIdx.x;
    const int warp = tid >> 5;
    const int lane = tid & 31;

    sv[tid] = v[tid];
    sqh[tid] = __halves2half2(g_qph[(size_t)(b * TQ + q0) * DD + tid],
                              g_qph[(size_t)(b * TQ + q0 + 1) * DD + tid]);

    const uint4* kp4 = (const uint4*)(g_kph + (size_t)b * DD * TH);   // 32 u4/row
    const int r_ = tid >> 5;          // staged row (16 rows, 8 threads... see idx)
    // staging index helper: idx = tid + s*256 (s<2); r = idx>>5, c = idx&31

    // ---- scores: s[q][t] = sum_d v[d] * tanh_f16(qp[q][d] + kp[d][t]) ----
    float acc0 = 0.f, acc1 = 0.f;
    uint4 pf[2];

    // prologue: chunk 0 -> buf0, prefetch chunk 1
#pragma unroll
    for (int s = 0; s < 2; s++) {
        int idx = tid + s * 256, r = idx >> 5, cc = idx & 31;
        pf[s] = kp4[r * 32 + cc];
    }
#pragma unroll
    for (int s = 0; s < 2; s++) {
        int idx = tid + s * 256, r = idx >> 5, cc = idx & 31;
        *(uint4*)&stage[0][r][cc * 8] = pf[s];
    }
#pragma unroll
    for (int s = 0; s < 2; s++) {
        int idx = tid + s * 256, r = idx >> 5, cc = idx & 31;
        pf[s] = kp4[(16 + r) * 32 + cc];
    }
    __syncthreads();

    for (int c = 0; c < 16; c++) {
        const int cur = c & 1, nxt = cur ^ 1;
        if (c < 15) {
#pragma unroll
            for (int s = 0; s < 2; s++) {
                int idx = tid + s * 256, r = idx >> 5, cc = idx & 31;
                *(uint4*)&stage[nxt][r][cc * 8] = pf[s];
            }
            if (c < 14) {
                const int d0n = (c + 2) * 16;
#pragma unroll
                for (int s = 0; s < 2; s++) {
                    int idx = tid + s * 256, r = idx >> 5, cc = idx & 31;
                    pf[s] = kp4[(d0n + r) * 32 + cc];
                }
            }
        }
        const int d0 = c * 16;
        float vr[16];
#pragma unroll
        for (int s = 0; s < 4; s++) {
            float4 vv = *(const float4*)&sv[d0 + s * 4];
            vr[s * 4 + 0] = vv.x; vr[s * 4 + 1] = vv.y;
            vr[s * 4 + 2] = vv.z; vr[s * 4 + 3] = vv.w;
        }
#pragma unroll
        for (int dd = 0; dd < 16; dd++) {
            __half2 xx = __half2half2(stage[cur][dd][tid]);  // LDS.U16 + dup
            __half2 s2 = __hadd2(sqh[d0 + dd], xx);
            float2 f  = __half22float2(tanh_f16x2(s2));
            acc0 = fmaf(vr[dd], f.x, acc0);
            acc1 = fmaf(vr[dd], f.y, acc1);
        }
        __syncthreads();
    }
    sc[0][tid] = acc0;
    sc[1][tid] = acc1;
    __syncthreads();

    // ---- softmax (unnormalized): warps 0-1, one query each ----
    if (warp < 2) {
        float ls[8];
        float m = -1e30f;
#pragma unroll
        for (int j = 0; j < 8; j++) {
            ls[j] = sc[warp][j * 32 + lane];
            m = fmaxf(m, ls[j]);
        }
#pragma unroll
        for (int o = 16; o; o >>= 1) m = fmaxf(m, __shfl_xor_sync(0xffffffffu, m, o));
        float ssum = 0.f;
#pragma unroll
        for (int j = 0; j < 8; j++) {
            ls[j] = __expf(ls[j] - m);
            ssum += ls[j];
        }
#pragma unroll
        for (int o = 16; o; o >>= 1) ssum += __shfl_xor_sync(0xffffffffu, ssum, o);
#pragma unroll
        for (int j = 0; j < 8; j++) sc[warp][j * 32 + lane] = ls[j];
        if (lane == 0) sinv[warp] = 1.f / ssum;
    }

    // ---- context[i] = (1/sum) * sum_t e[t] * keys_h[b][t][i]; i = tid ----
    float ctx0 = 0.f, ctx1 = 0.f;
    const uint4* kb4 = (const uint4*)(g_keysh + (size_t)b * TH * DIN);

#pragma unroll
    for (int s = 0; s < 2; s++) {
        int idx = tid + s * 256, r = idx >> 5, cc = idx & 31;
        pf[s] = kb4[r * 32 + cc];
    }
    __syncthreads();   // orders softmax writes for all warps
#pragma unroll
    for (int s = 0; s < 2; s++) {
        int idx = tid + s * 256, r = idx >> 5, cc = idx & 31;
        *(uint4*)&stage[0][r][cc * 8] = pf[s];
    }
#pragma unroll
    for (int s = 0; s < 2; s++) {
        int idx = tid + s * 256, r = idx >> 5, cc = idx & 31;
        pf[s] = kb4[(16 + r) * 32 + cc];
    }
    __syncthreads();

    for (int c = 0; c < 16; c++) {
        const int cur = c & 1, nxt = cur ^ 1;
        if (c < 15) {
#pragma unroll
            for (int s = 0; s < 2; s++) {
                int idx = tid + s * 256, r = idx >> 5, cc = idx & 31;
                *(uint4*)&stage[nxt][r][cc * 8] = pf[s];
            }
            if (c < 14) {
                const int t0n = (c + 2) * 16;
#pragma unroll
                for (int s = 0; s < 2; s++) {
                    int idx = tid + s * 256, r = idx >> 5, cc = idx & 31;
                    pf[s] = kb4[(t0n + r) * 32 + cc];
                }
            }
        }
        const int t0 = c * 16;
#pragma unroll
        for (int tg = 0; tg < 4; tg++) {
            float kv0 = __half2float(stage[cur][tg * 4 + 0][tid]);
            float kv1 = __half2float(stage[cur][tg * 4 + 1][tid]);
            float kv2 = __half2float(stage[cur][tg * 4 + 2][tid]);
            float kv3 = __half2float(stage[cur][tg * 4 + 3][tid]);
            float4 a0 = *(const float4*)&sc[0][t0 + tg * 4];
            float4 a1 = *(const float4*)&sc[1][t0 + tg * 4];
            ctx0 = fmaf(a0.x, kv0, fmaf(a0.y, kv1, fmaf(a0.z, kv2, fmaf(a0.w, kv3, ctx0))));
            ctx1 = fmaf(a1.x, kv0, fmaf(a1.y, kv1, fmaf(a1.z, kv2, fmaf(a1.w, kv3, ctx1))));
        }
        __syncthreads();
    }

    out[(size_t)(b * TQ + q0 + 0) * DIN + tid] = ctx0 * sinv[0];
    out[(size_t)(b * TQ + q0 + 1) * DIN + tid] = ctx1 * sinv[1];
}

// ---------------------------------------------------------------------------
// Launch. Inputs (metadata order): inputs, state, w1, w2, v, batch_size.
// Output: (B*TQ, DIN) float32.
// ---------------------------------------------------------------------------
extern "C" void kernel_launch(void* const* d_in, const int* in_sizes, int n_in,
                              void* d_out, int out_size)
{
    const float* inputs = (const float*)d_in[0];
    const float* state  = (const float*)d_in[1];
    const float* w1     = (const float*)d_in[2];
    const float* w2     = (const float*)d_in[3];
    const float* v      = (const float*)d_in[4];
    float* out = (float*)d_out;
    (void)in_sizes; (void)n_in; (void)out_size;

    proj_tc<<<192, 256>>>(inputs, state, w1, w2);   // 160 GEMM + 32 keys-f16 riders

    dim3 g2(TQ / 2, B_);       // (32, 32) = 1024 blocks, 2 queries each
    attn_kernel<<<g2, 256>>>(v, out);
}

// round 15
// speedup vs baseline: 1.4524x; 1.0074x over previous
#include <cuda_runtime.h>
#include <cuda_fp16.h>
#include <cstdint>

// Problem constants
#define B_    32
#define TH    256
#define TQ    64
#define DIN   256
#define DD    256
#define KD    256

// Scratch (allocation-free rule: __device__ globals)
__device__ __half g_kph  [B_ * DD * TH];   // 4 MB: [b][d][t] f16
__device__ __half g_qph  [B_ * TQ * DD];   // 1 MB: [q_global][d] f16
__device__ __half g_keysh[B_ * TH * DIN];  // 4 MB: [b][t][i] f16

// ---- f16x2 MUFU tanh (renamed: cuda_fp16.hpp owns h2tanh) ----
__device__ __forceinline__ __half2 tanh_f16x2(__half2 x) {
    unsigned xu = *(unsigned*)&x;
    unsigned ru;
    asm("tanh.approx.f16x2 %0, %1;" : "=r"(ru) : "r"(xu));
    return *(__half2*)&ru;
}

// ---- tf32 mma helpers ----
__device__ __forceinline__ unsigned f2tf(float f) {
    unsigned u; asm("cvt.rna.tf32.f32 %0, %1;" : "=r"(u) : "f"(f)); return u;
}
__device__ __forceinline__ void mma_tf32(
    float c[4], unsigned a0, unsigned a1, unsigned a2, unsigned a3,
    unsigned b0, unsigned b1)
{
    asm("mma.sync.aligned.m16n8k8.row.col.f32.tf32.tf32.f32 "
        "{%0,%1,%2,%3}, {%4,%5,%6,%7}, {%8,%9}, {%0,%1,%2,%3};"
        : "+f"(c[0]), "+f"(c[1]), "+f"(c[2]), "+f"(c[3])
        : "r"(a0), "r"(a1), "r"(a2), "r"(a3), "r"(b0), "r"(b1));
}

// ---------------------------------------------------------------------------
// Kernel 1: tf32 projection GEMMs, f16 outputs + keys f16 conversion riders.
//   blocks 0..127:   kph[b][d][t] = w1 @ inputs^T   (f16 store)
//   blocks 128..159: qph[q][d]    = state @ w2^T    (f16 store)
//   blocks 160..191: g_keysh[b] = f16(inputs[b])    (conversion riders)
// ---------------------------------------------------------------------------
#define BM   128
#define BN   128
#define BK   16
#define SPAD 20

__global__ __launch_bounds__(256, 2) void proj_tc(
    const float* __restrict__ inputs, const float* __restrict__ state,
    const float* __restrict__ w1, const float* __restrict__ w2)
{
    int id = blockIdx.x;

    if (id >= 160) {                  // keys f16 conversion riders
        const int bb = id - 160;
        const float4* src = (const float4*)(inputs + (size_t)bb * TH * DIN);
        __half2* dst = (__half2*)(g_keysh + (size_t)bb * TH * DIN);
        for (int i = threadIdx.x; i < TH * DIN / 4; i += 256) {
            float4 vv = src[i];
            dst[2 * i + 0] = __floats2half2_rn(vv.x, vv.y);
            dst[2 * i + 1] = __floats2half2_rn(vv.z, vv.w);
        }
        return;
    }

    __shared__ __align__(16) unsigned As[2][BM * SPAD];
    __shared__ __align__(16) unsigned Bs[2][BN * SPAD];

    const float* A;
    const float* Bsrc;
    int m0, n0;
    bool is_kp;
    if (id < 128) {            // GEMM1: kph
        is_kp = true;
        A = w1; Bsrc = inputs;
        m0 = (id & 1) * BM;
        n0 = (id >> 1) * BN;
    } else {                   // GEMM2: qph
        is_kp = false;
        id -= 128;
        A = state; Bsrc = w2;
        m0 = (id & 15) * BM;
        n0 = (id >> 4) * BN;
    }

    const int tid  = threadIdx.x;
    const int warp = tid >> 5, lane = tid & 31;
    const int g    = lane >> 2, tig = lane & 3;
    const int wm   = (warp >> 1) * 32;
    const int wn   = (warp & 1) * 64;

    const int srow = tid >> 1;
    const int sk4  = (tid & 1) * 8;
    const float* pa = A    + (size_t)(m0 + srow) * KD + sk4;
    const float* pb = Bsrc + (size_t)(n0 + srow) * KD + sk4;

    float acc[2][8][4];
#pragma unroll
    for (int mt = 0; mt < 2; mt++)
#pragma unroll
        for (int nt = 0; nt < 8; nt++)
#pragma unroll
            for (int i = 0; i < 4; i++) acc[mt][nt][i] = 0.f;

    float4 fa0, fa1, fb0, fb1;

    fa0 = *(const float4*)&pa[0];  fa1 = *(const float4*)&pa[4];
    fb0 = *(const float4*)&pb[0];  fb1 = *(const float4*)&pb[4];
    {
        uint4 u;
        u.x = f2tf(fa0.x); u.y = f2tf(fa0.y); u.z = f2tf(fa0.z); u.w = f2tf(fa0.w);
        *(uint4*)&As[0][srow * SPAD + sk4] = u;
        u.x = f2tf(fa1.x); u.y = f2tf(fa1.y); u.z = f2tf(fa1.z); u.w = f2tf(fa1.w);
        *(uint4*)&As[0][srow * SPAD + sk4 + 4] = u;
        u.x = f2tf(fb0.x); u.y = f2tf(fb0.y); u.z = f2tf(fb0.z); u.w = f2tf(fb0.w);
        *(uint4*)&Bs[0][srow * SPAD + sk4] = u;
        u.x = f2tf(fb1.x); u.y = f2tf(fb1.y); u.z = f2tf(fb1.z); u.w = f2tf(fb1.w);
        *(uint4*)&Bs[0][srow * SPAD + sk4 + 4] = u;
    }
    fa0 = *(const float4*)&pa[BK];  fa1 = *(const float4*)&pa[BK + 4];
    fb0 = *(const float4*)&pb[BK];  fb1 = *(const float4*)&pb[BK + 4];
    __syncthreads();

    for (int c = 0; c < KD / BK; c++) {
        const int cur = c & 1, nxt = cur ^ 1;
        if (c < 15) {
            uint4 u;
            u.x = f2tf(fa0.x); u.y = f2tf(fa0.y); u.z = f2tf(fa0.z); u.w = f2tf(fa0.w);
            *(uint4*)&As[nxt][srow * SPAD + sk4] = u;
            u.x = f2tf(fa1.x); u.y = f2tf(fa1.y); u.z = f2tf(fa1.z); u.w = f2tf(fa1.w);
            *(uint4*)&As[nxt][srow * SPAD + sk4 + 4] = u;
            u.x = f2tf(fb0.x); u.y = f2tf(fb0.y); u.z = f2tf(fb0.z); u.w = f2tf(fb0.w);
            *(uint4*)&Bs[nxt][srow * SPAD + sk4] = u;
            u.x = f2tf(fb1.x); u.y = f2tf(fb1.y); u.z = f2tf(fb1.z); u.w = f2tf(fb1.w);
            *(uint4*)&Bs[nxt][srow * SPAD + sk4 + 4] = u;
            if (c < 14) {
                const int ko = (c + 2) * BK;
                fa0 = *(const float4*)&pa[ko];  fa1 = *(const float4*)&pa[ko + 4];
                fb0 = *(const float4*)&pb[ko];  fb1 = *(const float4*)&pb[ko + 4];
            }
        }
#pragma unroll
        for (int ks = 0; ks < 2; ks++) {
            const int kb = ks * 8;
            unsigned a[2][4], b[8][2];
#pragma unroll
            for (int mt = 0; mt < 2; mt++) {
                const int r = wm + mt * 16 + g;
                a[mt][0] = As[cur][r * SPAD + kb + tig];
                a[mt][1] = As[cur][(r + 8) * SPAD + kb + tig];
                a[mt][2] = As[cur][r * SPAD + kb + tig + 4];
                a[mt][3] = As[cur][(r + 8) * SPAD + kb + tig + 4];
            }
#pragma unroll
            for (int nt = 0; nt < 8; nt++) {
                const int n = wn + nt * 8 + g;
                b[nt][0] = Bs[cur][n * SPAD + kb + tig];
                b[nt][1] = Bs[cur][n * SPAD + kb + tig + 4];
            }
#pragma unroll
            for (int mt = 0; mt < 2; mt++)
#pragma unroll
                for (int nt = 0; nt < 8; nt++)
                    mma_tf32(acc[mt][nt],
                             a[mt][0], a[mt][1], a[mt][2], a[mt][3],
                             b[nt][0], b[nt][1]);
        }
        __syncthreads();
    }

    if (is_kp) {
        const int bb = n0 >> 8;
        const int t0 = n0 & 255;
        __half* C = g_kph + (size_t)bb * DD * TH;
#pragma unroll
        for (int mt = 0; mt < 2; mt++) {
            const int row = m0 + wm + mt * 16 + g;
#pragma unroll
            for (int nt = 0; nt < 8; nt++) {
                const int col = t0 + wn + nt * 8 + 2 * tig;
                *(__half2*)&C[(size_t)row * TH + col] =
                    __floats2half2_rn(acc[mt][nt][0], acc[mt][nt][1]);
                *(__half2*)&C[(size_t)(row + 8) * TH + col] =
                    __floats2half2_rn(acc[mt][nt][2], acc[mt][nt][3]);
            }
        }
    } else {
#pragma unroll
        for (int mt = 0; mt < 2; mt++) {
            const int row = m0 + wm + mt * 16 + g;
#pragma unroll
            for (int nt = 0; nt < 8; nt++) {
                const int col = n0 + wn + nt * 8 + 2 * tig;
                *(__half2*)&g_qph[(size_t)row * DD + col] =
                    __floats2half2_rn(acc[mt][nt][0], acc[mt][nt][1]);
                *(__half2*)&g_qph[(size_t)(row + 8) * DD + col] =
                    __floats2half2_rn(acc[mt][nt][2], acc[mt][nt][3]);
            }
        }
    }
}

// ---------------------------------------------------------------------------
// Kernel 2: scores + softmax + context. grid (TQ/2, B) = 1024 blocks, 256
// threads, 2 queries/block. Score phase: f16x2 HADD+tanh+HFMA2, windowed
// (4 d per window) promotion to f32. Context: f32 FMA.
// ---------------------------------------------------------------------------
#define HPAD 264   // halves per staged row (33 uint4)

__global__ __launch_bounds__(256) void attn_kernel(
    const float* __restrict__ v, float* __restrict__ out)
{
    __shared__ __align__(16) __half stage[2][16][HPAD];  // 16.9 KB
    __shared__ __align__(16) float sc[2][256];           // exp(scores)
    __shared__ __align__(16) __half2 sqh[256];           // {q0,q1} per d
    __shared__ __align__(16) __half2 sv2[256];           // {v,v} per d (f16)
    __shared__ float sinv[2];

    const int b    = blockIdx.y;
    const int q0   = blockIdx.x * 2;
    const int tid  = threadIdx.x;
    const int warp = tid >> 5;
    const int lane = tid & 31;

    sv2[tid] = __float2half2_rn(v[tid]);
    sqh[tid] = __halves2half2(g_qph[(size_t)(b * TQ + q0) * DD + tid],
                              g_qph[(size_t)(b * TQ + q0 + 1) * DD + tid]);

    const uint4* kp4 = (const uint4*)(g_kph + (size_t)b * DD * TH);   // 32 u4/row

    // ---- scores: s[q][t] = sum_d v[d] * tanh_f16(qp[q][d] + kp[d][t]) ----
    float acc0 = 0.f, acc1 = 0.f;
    uint4 pf[2];

    // prologue: chunk 0 -> buf0, prefetch chunk 1
#pragma unroll
    for (int s = 0; s < 2; s++) {
        int idx = tid + s * 256, r = idx >> 5, cc = idx & 31;
        pf[s] = kp4[r * 32 + cc];
    }
#pragma unroll
    for (int s = 0; s < 2; s++) {
        int idx = tid + s * 256, r = idx >> 5, cc = idx & 31;
        *(uint4*)&stage[0][r][cc * 8] = pf[s];
    }
#pragma unroll
    for (int s = 0; s < 2; s++) {
        int idx = tid + s * 256, r = idx >> 5, cc = idx & 31;
        pf[s] = kp4[(16 + r) * 32 + cc];
    }
    __syncthreads();

    for (int c = 0; c < 16; c++) {
        const int cur = c & 1, nxt = cur ^ 1;
        if (c < 15) {
#pragma unroll
            for (int s = 0; s < 2; s++) {
                int idx = tid + s * 256, r = idx >> 5, cc = idx & 31;
                *(uint4*)&stage[nxt][r][cc * 8] = pf[s];
            }
            if (c < 14) {
                const int d0n = (c + 2) * 16;
#pragma unroll
                for (int s = 0; s < 2; s++) {
                    int idx = tid + s * 256, r = idx >> 5, cc = idx & 31;
                    pf[s] = kp4[(d0n + r) * 32 + cc];
                }
            }
        }
        const int d0 = c * 16;
        // v (dup'd f16 pairs) for this chunk: 16 half2 = 64 B = FOUR uint4
        __half2 vv2[16];
        *(uint4*)&vv2[0]  = *(const uint4*)&sv2[d0];
        *(uint4*)&vv2[4]  = *(const uint4*)&sv2[d0 + 4];
        *(uint4*)&vv2[8]  = *(const uint4*)&sv2[d0 + 8];
        *(uint4*)&vv2[12] = *(const uint4*)&sv2[d0 + 12];
        // 4 windows of 4 d-steps; f16 accumulate within, f32 across
#pragma unroll
        for (int w = 0; w < 4; w++) {
            __half2 hacc;
            {
                const int dd = w * 4;
                __half2 xx = __half2half2(stage[cur][dd][tid]);
                __half2 th = tanh_f16x2(__hadd2(sqh[d0 + dd], xx));
                hacc = __hmul2(vv2[dd], th);
            }
#pragma unroll
            for (int j = 1; j < 4; j++) {
                const int dd = w * 4 + j;
                __half2 xx = __half2half2(stage[cur][dd][tid]);
                __half2 th = tanh_f16x2(__hadd2(sqh[d0 + dd], xx));
                hacc = __hfma2(vv2[dd], th, hacc);
            }
            float2 f = __half22float2(hacc);
            acc0 += f.x;
            acc1 += f.y;
        }
        __syncthreads();
    }
    sc[0][tid] = acc0;
    sc[1][tid] = acc1;
    __syncthreads();

    // ---- softmax (unnormalized): warps 0-1, one query each ----
    if (warp < 2) {
        float ls[8];
        float m = -1e30f;
#pragma unroll
        for (int j = 0; j < 8; j++) {
            ls[j] = sc[warp][j * 32 + lane];
            m = fmaxf(m, ls[j]);
        }
#pragma unroll
        for (int o = 16; o; o >>= 1) m = fmaxf(m, __shfl_xor_sync(0xffffffffu, m, o));
        float ssum = 0.f;
#pragma unroll
        for (int j = 0; j < 8; j++) {
            ls[j] = __expf(ls[j] - m);
            ssum += ls[j];
        }
#pragma unroll
        for (int o = 16; o; o >>= 1) ssum += __shfl_xor_sync(0xffffffffu, ssum, o);
#pragma unroll
        for (int j = 0; j < 8; j++) sc[warp][j * 32 + lane] = ls[j];
        if (lane == 0) sinv[warp] = 1.f / ssum;
    }

    // ---- context[i] = (1/sum) * sum_t e[t] * keys_h[b][t][i]; i = tid ----
    float ctx0 = 0.f, ctx1 = 0.f;
    const uint4* kb4 = (const uint4*)(g_keysh + (size_t)b * TH * DIN);

#pragma unroll
    for (int s = 0; s < 2; s++) {
        int idx = tid + s * 256, r = idx >> 5, cc = idx & 31;
        pf[s] = kb4[r * 32 + cc];
    }
    __syncthreads();   // orders softmax writes for all warps
#pragma unroll
    for (int s = 0; s < 2; s++) {
        int idx = tid + s * 256, r = idx >> 5, cc = idx & 31;
        *(uint4*)&stage[0][r][cc * 8] = pf[s];
    }
#pragma unroll
    for (int s = 0; s < 2; s++) {
        int idx = tid + s * 256, r = idx >> 5, cc = idx & 31;
        pf[s] = kb4[(16 + r) * 32 + cc];
    }
    __syncthreads();

    for (int c = 0; c < 16; c++) {
        const int cur = c & 1, nxt = cur ^ 1;
        if (c < 15) {
#pragma unroll
            for (int s = 0; s < 2; s++) {
                int idx = tid + s * 256, r = idx >> 5, cc = idx & 31;
                *(uint4*)&stage[nxt][r][cc * 8] = pf[s];
            }
            if (c < 14) {
                const int t0n = (c + 2) * 16;
#pragma unroll
                for (int s = 0; s < 2; s++) {
                    int idx = tid + s * 256, r = idx >> 5, cc = idx & 31;
                    pf[s] = kb4[(t0n + r) * 32 + cc];
                }
            }
        }
        const int t0 = c * 16;
#pragma unroll
        for (int tg = 0; tg < 4; tg++) {
            float kv0 = __half2float(stage[cur][tg * 4 + 0][tid]);
            float kv1 = __half2float(stage[cur][tg * 4 + 1][tid]);
            float kv2 = __half2float(stage[cur][tg * 4 + 2][tid]);
            float kv3 = __half2float(stage[cur][tg * 4 + 3][tid]);
            float4 a0 = *(const float4*)&sc[0][t0 + tg * 4];
            float4 a1 = *(const float4*)&sc[1][t0 + tg * 4];
            ctx0 = fmaf(a0.x, kv0, fmaf(a0.y, kv1, fmaf(a0.z, kv2, fmaf(a0.w, kv3, ctx0))));
            ctx1 = fmaf(a1.x, kv0, fmaf(a1.y, kv1, fmaf(a1.z, kv2, fmaf(a1.w, kv3, ctx1))));
        }
        __syncthreads();
    }

    out[(size_t)(b * TQ + q0 + 0) * DIN + tid] = ctx0 * sinv[0];
    out[(size_t)(b * TQ + q0 + 1) * DIN + tid] = ctx1 * sinv[1];
}

// ---------------------------------------------------------------------------
// Launch. Inputs (metadata order): inputs, state, w1, w2, v, batch_size.
// Output: (B*TQ, DIN) float32.
// ---------------------------------------------------------------------------
extern "C" void kernel_launch(void* const* d_in, const int* in_sizes, int n_in,
                              void* d_out, int out_size)
{
    const float* inputs = (const float*)d_in[0];
    const float* state  = (const float*)d_in[1];
    const float* w1     = (const float*)d_in[2];
    const float* w2     = (const float*)d_in[3];
    const float* v      = (const float*)d_in[4];
    float* out = (float*)d_out;
    (void)in_sizes; (void)n_in; (void)out_size;

    proj_tc<<<192, 256>>>(inputs, state, w1, w2);   // 160 GEMM + 32 keys-f16 riders

    dim3 g2(TQ / 2, B_);       // (32, 32) = 1024 blocks, 2 queries each
    attn_kernel<<<g2, 256>>>(v, out);
}

// round 16
// speedup vs baseline: 1.4759x; 1.0162x over previous
#include <cuda_runtime.h>
#include <cuda_fp16.h>
#include <cstdint>

// Problem constants
#define B_    32
#define TH    256
#define TQ    64
#define DIN   256
#define DD    256
#define KD    256

// Scratch (allocation-free rule: __device__ globals)
__device__ __half g_kph  [B_ * DD * TH];   // 4 MB: [b][d][t] f16
__device__ __half g_qph  [B_ * TQ * DD];   // 1 MB: [q_global][d] f16
__device__ __half g_keysh[B_ * TH * DIN];  // 4 MB: [b][t][i] f16

// ---- f16x2 MUFU tanh (renamed: cuda_fp16.hpp owns h2tanh) ----
__device__ __forceinline__ __half2 tanh_f16x2(__half2 x) {
    unsigned xu = *(unsigned*)&x;
    unsigned ru;
    asm("tanh.approx.f16x2 %0, %1;" : "=r"(ru) : "r"(xu));
    return *(__half2*)&ru;
}

// ---- tf32 mma helpers ----
__device__ __forceinline__ unsigned f2tf(float f) {
    unsigned u; asm("cvt.rna.tf32.f32 %0, %1;" : "=r"(u) : "f"(f)); return u;
}
__device__ __forceinline__ void mma_tf32(
    float c[4], unsigned a0, unsigned a1, unsigned a2, unsigned a3,
    unsigned b0, unsigned b1)
{
    asm("mma.sync.aligned.m16n8k8.row.col.f32.tf32.tf32.f32 "
        "{%0,%1,%2,%3}, {%4,%5,%6,%7}, {%8,%9}, {%0,%1,%2,%3};"
        : "+f"(c[0]), "+f"(c[1]), "+f"(c[2]), "+f"(c[3])
        : "r"(a0), "r"(a1), "r"(a2), "r"(a3), "r"(b0), "r"(b1));
}

// ---------------------------------------------------------------------------
// Kernel 1: tf32 projection GEMMs, f16 outputs + keys f16 conversion riders.
// (unchanged from R14)
// ---------------------------------------------------------------------------
#define BM   128
#define BN   128
#define BK   16
#define SPAD 20

__global__ __launch_bounds__(256, 2) void proj_tc(
    const float* __restrict__ inputs, const float* __restrict__ state,
    const float* __restrict__ w1, const float* __restrict__ w2)
{
    int id = blockIdx.x;

    if (id >= 160) {                  // keys f16 conversion riders
        const int bb = id - 160;
        const float4* src = (const float4*)(inputs + (size_t)bb * TH * DIN);
        __half2* dst = (__half2*)(g_keysh + (size_t)bb * TH * DIN);
        for (int i = threadIdx.x; i < TH * DIN / 4; i += 256) {
            float4 vv = src[i];
            dst[2 * i + 0] = __floats2half2_rn(vv.x, vv.y);
            dst[2 * i + 1] = __floats2half2_rn(vv.z, vv.w);
        }
        return;
    }

    __shared__ __align__(16) unsigned As[2][BM * SPAD];
    __shared__ __align__(16) unsigned Bs[2][BN * SPAD];

    const float* A;
    const float* Bsrc;
    int m0, n0;
    bool is_kp;
    if (id < 128) {            // GEMM1: kph
        is_kp = true;
        A = w1; Bsrc = inputs;
        m0 = (id & 1) * BM;
        n0 = (id >> 1) * BN;
    } else {                   // GEMM2: qph
        is_kp = false;
        id -= 128;
        A = state; Bsrc = w2;
        m0 = (id & 15) * BM;
        n0 = (id >> 4) * BN;
    }

    const int tid  = threadIdx.x;
    const int warp = tid >> 5, lane = tid & 31;
    const int g    = lane >> 2, tig = lane & 3;
    const int wm   = (warp >> 1) * 32;
    const int wn   = (warp & 1) * 64;

    const int srow = tid >> 1;
    const int sk4  = (tid & 1) * 8;
    const float* pa = A    + (size_t)(m0 + srow) * KD + sk4;
    const float* pb = Bsrc + (size_t)(n0 + srow) * KD + sk4;

    float acc[2][8][4];
#pragma unroll
    for (int mt = 0; mt < 2; mt++)
#pragma unroll
        for (int nt = 0; nt < 8; nt++)
#pragma unroll
            for (int i = 0; i < 4; i++) acc[mt][nt][i] = 0.f;

    float4 fa0, fa1, fb0, fb1;

    fa0 = *(const float4*)&pa[0];  fa1 = *(const float4*)&pa[4];
    fb0 = *(const float4*)&pb[0];  fb1 = *(const float4*)&pb[4];
    {
        uint4 u;
        u.x = f2tf(fa0.x); u.y = f2tf(fa0.y); u.z = f2tf(fa0.z); u.w = f2tf(fa0.w);
        *(uint4*)&As[0][srow * SPAD + sk4] = u;
        u.x = f2tf(fa1.x); u.y = f2tf(fa1.y); u.z = f2tf(fa1.z); u.w = f2tf(fa1.w);
        *(uint4*)&As[0][srow * SPAD + sk4 + 4] = u;
        u.x = f2tf(fb0.x); u.y = f2tf(fb0.y); u.z = f2tf(fb0.z); u.w = f2tf(fb0.w);
        *(uint4*)&Bs[0][srow * SPAD + sk4] = u;
        u.x = f2tf(fb1.x); u.y = f2tf(fb1.y); u.z = f2tf(fb1.z); u.w = f2tf(fb1.w);
        *(uint4*)&Bs[0][srow * SPAD + sk4 + 4] = u;
    }
    fa0 = *(const float4*)&pa[BK];  fa1 = *(const float4*)&pa[BK + 4];
    fb0 = *(const float4*)&pb[BK];  fb1 = *(const float4*)&pb[BK + 4];
    __syncthreads();

    for (int c = 0; c < KD / BK; c++) {
        const int cur = c & 1, nxt = cur ^ 1;
        if (c < 15) {
            uint4 u;
            u.x = f2tf(fa0.x); u.y = f2tf(fa0.y); u.z = f2tf(fa0.z); u.w = f2tf(fa0.w);
            *(uint4*)&As[nxt][srow * SPAD + sk4] = u;
            u.x = f2tf(fa1.x); u.y = f2tf(fa1.y); u.z = f2tf(fa1.z); u.w = f2tf(fa1.w);
            *(uint4*)&As[nxt][srow * SPAD + sk4 + 4] = u;
            u.x = f2tf(fb0.x); u.y = f2tf(fb0.y); u.z = f2tf(fb0.z); u.w = f2tf(fb0.w);
            *(uint4*)&Bs[nxt][srow * SPAD + sk4] = u;
            u.x = f2tf(fb1.x); u.y = f2tf(fb1.y); u.z = f2tf(fb1.z); u.w = f2tf(fb1.w);
            *(uint4*)&Bs[nxt][srow * SPAD + sk4 + 4] = u;
            if (c < 14) {
                const int ko = (c + 2) * BK;
                fa0 = *(const float4*)&pa[ko];  fa1 = *(const float4*)&pa[ko + 4];
                fb0 = *(const float4*)&pb[ko];  fb1 = *(const float4*)&pb[ko + 4];
            }
        }
#pragma unroll
        for (int ks = 0; ks < 2; ks++) {
            const int kb = ks * 8;
            unsigned a[2][4], b[8][2];
#pragma unroll
            for (int mt = 0; mt < 2; mt++) {
                const int r = wm + mt * 16 + g;
                a[mt][0] = As[cur][r * SPAD + kb + tig];
                a[mt][1] = As[cur][(r + 8) * SPAD + kb + tig];
                a[mt][2] = As[cur][r * SPAD + kb + tig + 4];
                a[mt][3] = As[cur][(r + 8) * SPAD + kb + tig + 4];
            }
#pragma unroll
            for (int nt = 0; nt < 8; nt++) {
                const int n = wn + nt * 8 + g;
                b[nt][0] = Bs[cur][n * SPAD + kb + tig];
                b[nt][1] = Bs[cur][n * SPAD + kb + tig + 4];
            }
#pragma unroll
            for (int mt = 0; mt < 2; mt++)
#pragma unroll
                for (int nt = 0; nt < 8; nt++)
                    mma_tf32(acc[mt][nt],
                             a[mt][0], a[mt][1], a[mt][2], a[mt][3],
                             b[nt][0], b[nt][1]);
        }
        __syncthreads();
    }

    if (is_kp) {
        const int bb = n0 >> 8;
        const int t0 = n0 & 255;
        __half* C = g_kph + (size_t)bb * DD * TH;
#pragma unroll
        for (int mt = 0; mt < 2; mt++) {
            const int row = m0 + wm + mt * 16 + g;
#pragma unroll
            for (int nt = 0; nt < 8; nt++) {
                const int col = t0 + wn + nt * 8 + 2 * tig;
                *(__half2*)&C[(size_t)row * TH + col] =
                    __floats2half2_rn(acc[mt][nt][0], acc[mt][nt][1]);
                *(__half2*)&C[(size_t)(row + 8) * TH + col] =
                    __floats2half2_rn(acc[mt][nt][2], acc[mt][nt][3]);
            }
        }
    } else {
#pragma unroll
        for (int mt = 0; mt < 2; mt++) {
            const int row = m0 + wm + mt * 16 + g;
#pragma unroll
            for (int nt = 0; nt < 8; nt++) {
                const int col = n0 + wn + nt * 8 + 2 * tig;
                *(__half2*)&g_qph[(size_t)row * DD + col] =
                    __floats2half2_rn(acc[mt][nt][0], acc[mt][nt][1]);
                *(__half2*)&g_qph[(size_t)(row + 8) * DD + col] =
                    __floats2half2_rn(acc[mt][nt][2], acc[mt][nt][3]);
            }
        }
    }
}

// ---------------------------------------------------------------------------
// Kernel 2: scores + softmax + context. grid (TQ/2, B) = 1024 blocks, 256
// threads, 2 queries/block.
// Score phase: thread owns a t-PAIR (ti = tid&127 -> t = 2ti, 2ti+1); d-rows
// of each chunk split across thread-halves (half = tid>>7: rows 0-7 / 8-15).
// One LDS.U32 feeds 2 t; q-broadcasts pre-dup'd (sq0/sq1) - no PRMT dups.
// f16 window-4 accumulation, f32 across windows; cross-half combine via smem.
// Context: f32 FMA (unchanged).
// ---------------------------------------------------------------------------
#define HPAD 264   // halves per staged row (33 uint4)

__global__ __launch_bounds__(256) void attn_kernel(
    const float* __restrict__ v, float* __restrict__ out)
{
    __shared__ __align__(16) __half stage[2][16][HPAD];  // 16.9 KB
    __shared__ __align__(16) float sc[2][256];           // exp(scores)
    __shared__ __align__(16) __half2 sq0[256];           // {q0,q0} per d
    __shared__ __align__(16) __half2 sq1[256];           // {q1,q1} per d
    __shared__ __align__(16) __half2 sv2[256];           // {v,v} per d (f16)
    __shared__ __align__(16) float part[4][128];         // cross-half partials
    __shared__ float sinv[2];

    const int b    = blockIdx.y;
    const int q0   = blockIdx.x * 2;
    const int tid  = threadIdx.x;
    const int warp = tid >> 5;
    const int lane = tid & 31;
    const int ti   = tid & 127;     // t-pair index
    const int half = tid >> 7;      // d-row half
    const int rb   = half * 8;      // d-row base within chunk

    sv2[tid] = __float2half2_rn(v[tid]);
    sq0[tid] = __half2half2(g_qph[(size_t)(b * TQ + q0 + 0) * DD + tid]);
    sq1[tid] = __half2half2(g_qph[(size_t)(b * TQ + q0 + 1) * DD + tid]);

    const uint4* kp4 = (const uint4*)(g_kph + (size_t)b * DD * TH);   // 32 u4/row

    // ---- scores: s[q][t] = sum_d v[d] * tanh_f16(qp[q][d] + kp[d][t]) ----
    float a00 = 0.f, a01 = 0.f, a10 = 0.f, a11 = 0.f;  // [q][t-pos]
    uint4 pf[2];

    // prologue: chunk 0 -> buf0, prefetch chunk 1
#pragma unroll
    for (int s = 0; s < 2; s++) {
        int idx = tid + s * 256, r = idx >> 5, cc = idx & 31;
        pf[s] = kp4[r * 32 + cc];
    }
#pragma unroll
    for (int s = 0; s < 2; s++) {
        int idx = tid + s * 256, r = idx >> 5, cc = idx & 31;
        *(uint4*)&stage[0][r][cc * 8] = pf[s];
    }
#pragma unroll
    for (int s = 0; s < 2; s++) {
        int idx = tid + s * 256, r = idx >> 5, cc = idx & 31;
        pf[s] = kp4[(16 + r) * 32 + cc];
    }
    __syncthreads();

    for (int c = 0; c < 16; c++) {
        const int cur = c & 1, nxt = cur ^ 1;
        if (c < 15) {
#pragma unroll
            for (int s = 0; s < 2; s++) {
                int idx = tid + s * 256, r = idx >> 5, cc = idx & 31;
                *(uint4*)&stage[nxt][r][cc * 8] = pf[s];
            }
            if (c < 14) {
                const int d0n = (c + 2) * 16;
#pragma unroll
                for (int s = 0; s < 2; s++) {
                    int idx = tid + s * 256, r = idx >> 5, cc = idx & 31;
                    pf[s] = kp4[(d0n + r) * 32 + cc];
                }
            }
        }
        const int d0 = c * 16;
        // v dup'd pairs for this thread's 8 d-rows: 8 half2 = 2 uint4
        __half2 vv2[8];
        *(uint4*)&vv2[0] = *(const uint4*)&sv2[d0 + rb];
        *(uint4*)&vv2[4] = *(const uint4*)&sv2[d0 + rb + 4];
        // 2 windows of 4 d-steps; f16 accumulate within, f32 across
#pragma unroll
        for (int w = 0; w < 2; w++) {
            __half2 h0, h1;
            {
                const int k = w * 4;
                const int dd = rb + k;
                __half2 kt = *(const __half2*)&stage[cur][dd][2 * ti];
                h0 = __hmul2(vv2[k], tanh_f16x2(__hadd2(sq0[d0 + dd], kt)));
                h1 = __hmul2(vv2[k], tanh_f16x2(__hadd2(sq1[d0 + dd], kt)));
            }
#pragma unroll
            for (int j = 1; j < 4; j++) {
                const int k = w * 4 + j;
                const int dd = rb + k;
                __half2 kt = *(const __half2*)&stage[cur][dd][2 * ti];
                h0 = __hfma2(vv2[k], tanh_f16x2(__hadd2(sq0[d0 + dd], kt)), h0);
                h1 = __hfma2(vv2[k], tanh_f16x2(__hadd2(sq1[d0 + dd], kt)), h1);
            }
            float2 f0 = __half22float2(h0);
            float2 f1 = __half22float2(h1);
            a00 += f0.x; a01 += f0.y;
            a10 += f1.x; a11 += f1.y;
        }
        __syncthreads();
    }

    // cross-half combine: half 1 publishes, half 0 reduces + writes sc
    if (half) {
        part[0][ti] = a00; part[1][ti] = a01;
        part[2][ti] = a10; part[3][ti] = a11;
    }
    __syncthreads();
    if (!half) {
        sc[0][2 * ti + 0] = a00 + part[0][ti];
        sc[0][2 * ti + 1] = a01 + part[1][ti];
        sc[1][2 * ti + 0] = a10 + part[2][ti];
        sc[1][2 * ti + 1] = a11 + part[3][ti];
    }
    __syncthreads();

    // ---- softmax (unnormalized): warps 0-1, one query each ----
    if (warp < 2) {
        float ls[8];
        float m = -1e30f;
#pragma unroll
        for (int j = 0; j < 8; j++) {
            ls[j] = sc[warp][j * 32 + lane];
            m = fmaxf(m, ls[j]);
        }
#pragma unroll
        for (int o = 16; o; o >>= 1) m = fmaxf(m, __shfl_xor_sync(0xffffffffu, m, o));
        float ssum = 0.f;
#pragma unroll
        for (int j = 0; j < 8; j++) {
            ls[j] = __expf(ls[j] - m);
            ssum += ls[j];
        }
#pragma unroll
        for (int o = 16; o; o >>= 1) ssum += __shfl_xor_sync(0xffffffffu, ssum, o);
#pragma unroll
        for (int j = 0; j < 8; j++) sc[warp][j * 32 + lane] = ls[j];
        if (lane == 0) sinv[warp] = 1.f / ssum;
    }

    // ---- context[i] = (1/sum) * sum_t e[t] * keys_h[b][t][i]; i = tid ----
    float ctx0 = 0.f, ctx1 = 0.f;
    const uint4* kb4 = (const uint4*)(g_keysh + (size_t)b * TH * DIN);

#pragma unroll
    for (int s = 0; s < 2; s++) {
        int idx = tid + s * 256, r = idx >> 5, cc = idx & 31;
        pf[s] = kb4[r * 32 + cc];
    }
    __syncthreads();   // orders softmax writes for all warps
#pragma unroll
    for (int s = 0; s < 2; s++) {
        int idx = tid + s * 256, r = idx >> 5, cc = idx & 31;
        *(uint4*)&stage[0][r][cc * 8] = pf[s];
    }
#pragma unroll
    for (int s = 0; s < 2; s++) {
        int idx = tid + s * 256, r = idx >> 5, cc = idx & 31;
        pf[s] = kb4[(16 + r) * 32 + cc];
    }
    __syncthreads();

    for (int c = 0; c < 16; c++) {
        const int cur = c & 1, nxt = cur ^ 1;
        if (c < 15) {
#pragma unroll
            for (int s = 0; s < 2; s++) {
                int idx = tid + s * 256, r = idx >> 5, cc = idx & 31;
                *(uint4*)&stage[nxt][r][cc * 8] = pf[s];
            }
            if (c < 14) {
                const int t0n = (c + 2) * 16;
#pragma unroll
                for (int s = 0; s < 2; s++) {
                    int idx = tid + s * 256, r = idx >> 5, cc = idx & 31;
                    pf[s] = kb4[(t0n + r) * 32 + cc];
                }
            }
        }
        const int t0 = c * 16;
#pragma unroll
        for (int tg = 0; tg < 4; tg++) {
            float kv0 = __half2float(stage[cur][tg * 4 + 0][tid]);
            float kv1 = __half2float(stage[cur][tg * 4 + 1][tid]);
            float kv2 = __half2float(stage[cur][tg * 4 + 2][tid]);
            float kv3 = __half2float(stage[cur][tg * 4 + 3][tid]);
            float4 a0 = *(const float4*)&sc[0][t0 + tg * 4];
            float4 a1 = *(const float4*)&sc[1][t0 + tg * 4];
            ctx0 = fmaf(a0.x, kv0, fmaf(a0.y, kv1, fmaf(a0.z, kv2, fmaf(a0.w, kv3, ctx0))));
            ctx1 = fmaf(a1.x, kv0, fmaf(a1.y, kv1, fmaf(a1.z, kv2, fmaf(a1.w, kv3, ctx1))));
        }
        __syncthreads();
    }

    out[(size_t)(b * TQ + q0 + 0) * DIN + tid] = ctx0 * sinv[0];
    out[(size_t)(b * TQ + q0 + 1) * DIN + tid] = ctx1 * sinv[1];
}

// ---------------------------------------------------------------------------
// Launch. Inputs (metadata order): inputs, state, w1, w2, v, batch_size.
// Output: (B*TQ, DIN) float32.
// ---------------------------------------------------------------------------
extern "C" void kernel_launch(void* const* d_in, const int* in_sizes, int n_in,
                              void* d_out, int out_size)
{
    const float* inputs = (const float*)d_in[0];
    const float* state  = (const float*)d_in[1];
    const float* w1     = (const float*)d_in[2];
    const float* w2     = (const float*)d_in[3];
    const float* v      = (const float*)d_in[4];
    float* out = (float*)d_out;
    (void)in_sizes; (void)n_in; (void)out_size;

    proj_tc<<<192, 256>>>(inputs, state, w1, w2);   // 160 GEMM + 32 keys-f16 riders

    dim3 g2(TQ / 2, B_);       // (32, 32) = 1024 blocks, 2 queries each
    attn_kernel<<<g2, 256>>>(v, out);
}

// round 17
// speedup vs baseline: 1.5290x; 1.0360x over previous
#include <cuda_runtime.h>
#include <cuda_fp16.h>
#include <cstdint>

// Problem constants
#define B_    32
#define TH    256
#define TQ    64
#define DIN   256
#define DD    256
#define KD    256

// Scratch (allocation-free rule: __device__ globals)
__device__ __half g_kph  [B_ * DD * TH];   // 4 MB: [b][d][t] f16
__device__ __half g_qph  [B_ * TQ * DD];   // 1 MB: [q_global][d] f16
__device__ __half g_keysh[B_ * TH * DIN];  // 4 MB: [b][t][i] f16

// ---- f16x2 MUFU tanh (renamed: cuda_fp16.hpp owns h2tanh) ----
__device__ __forceinline__ __half2 tanh_f16x2(__half2 x) {
    unsigned xu = *(unsigned*)&x;
    unsigned ru;
    asm("tanh.approx.f16x2 %0, %1;" : "=r"(ru) : "r"(xu));
    return *(__half2*)&ru;
}

// ---- tf32 mma helpers ----
__device__ __forceinline__ unsigned f2tf(float f) {
    unsigned u; asm("cvt.rna.tf32.f32 %0, %1;" : "=r"(u) : "f"(f)); return u;
}
__device__ __forceinline__ void mma_tf32(
    float c[4], unsigned a0, unsigned a1, unsigned a2, unsigned a3,
    unsigned b0, unsigned b1)
{
    asm("mma.sync.aligned.m16n8k8.row.col.f32.tf32.tf32.f32 "
        "{%0,%1,%2,%3}, {%4,%5,%6,%7}, {%8,%9}, {%0,%1,%2,%3};"
        : "+f"(c[0]), "+f"(c[1]), "+f"(c[2]), "+f"(c[3])
        : "r"(a0), "r"(a1), "r"(a2), "r"(a3), "r"(b0), "r"(b1));
}

// ---------------------------------------------------------------------------
// Kernel 1: tf32 projection GEMMs, f16 outputs + keys f16 conversion riders.
// (unchanged)
// ---------------------------------------------------------------------------
#define BM   128
#define BN   128
#define BK   16
#define SPAD 20

__global__ __launch_bounds__(256, 2) void proj_tc(
    const float* __restrict__ inputs, const float* __restrict__ state,
    const float* __restrict__ w1, const float* __restrict__ w2)
{
    int id = blockIdx.x;

    if (id >= 160) {                  // keys f16 conversion riders
        const int bb = id - 160;
        const float4* src = (const float4*)(inputs + (size_t)bb * TH * DIN);
        __half2* dst = (__half2*)(g_keysh + (size_t)bb * TH * DIN);
        for (int i = threadIdx.x; i < TH * DIN / 4; i += 256) {
            float4 vv = src[i];
            dst[2 * i + 0] = __floats2half2_rn(vv.x, vv.y);
            dst[2 * i + 1] = __floats2half2_rn(vv.z, vv.w);
        }
        return;
    }

    __shared__ __align__(16) unsigned As[2][BM * SPAD];
    __shared__ __align__(16) unsigned Bs[2][BN * SPAD];

    const float* A;
    const float* Bsrc;
    int m0, n0;
    bool is_kp;
    if (id < 128) {            // GEMM1: kph
        is_kp = true;
        A = w1; Bsrc = inputs;
        m0 = (id & 1) * BM;
        n0 = (id >> 1) * BN;
    } else {                   // GEMM2: qph
        is_kp = false;
        id -= 128;
        A = state; Bsrc = w2;
        m0 = (id & 15) * BM;
        n0 = (id >> 4) * BN;
    }

    const int tid  = threadIdx.x;
    const int warp = tid >> 5, lane = tid & 31;
    const int g    = lane >> 2, tig = lane & 3;
    const int wm   = (warp >> 1) * 32;
    const int wn   = (warp & 1) * 64;

    const int srow = tid >> 1;
    const int sk4  = (tid & 1) * 8;
    const float* pa = A    + (size_t)(m0 + srow) * KD + sk4;
    const float* pb = Bsrc + (size_t)(n0 + srow) * KD + sk4;

    float acc[2][8][4];
#pragma unroll
    for (int mt = 0; mt < 2; mt++)
#pragma unroll
        for (int nt = 0; nt < 8; nt++)
#pragma unroll
            for (int i = 0; i < 4; i++) acc[mt][nt][i] = 0.f;

    float4 fa0, fa1, fb0, fb1;

    fa0 = *(const float4*)&pa[0];  fa1 = *(const float4*)&pa[4];
    fb0 = *(const float4*)&pb[0];  fb1 = *(const float4*)&pb[4];
    {
        uint4 u;
        u.x = f2tf(fa0.x); u.y = f2tf(fa0.y); u.z = f2tf(fa0.z); u.w = f2tf(fa0.w);
        *(uint4*)&As[0][srow * SPAD + sk4] = u;
        u.x = f2tf(fa1.x); u.y = f2tf(fa1.y); u.z = f2tf(fa1.z); u.w = f2tf(fa1.w);
        *(uint4*)&As[0][srow * SPAD + sk4 + 4] = u;
        u.x = f2tf(fb0.x); u.y = f2tf(fb0.y); u.z = f2tf(fb0.z); u.w = f2tf(fb0.w);
        *(uint4*)&Bs[0][srow * SPAD + sk4] = u;
        u.x = f2tf(fb1.x); u.y = f2tf(fb1.y); u.z = f2tf(fb1.z); u.w = f2tf(fb1.w);
        *(uint4*)&Bs[0][srow * SPAD + sk4 + 4] = u;
    }
    fa0 = *(const float4*)&pa[BK];  fa1 = *(const float4*)&pa[BK + 4];
    fb0 = *(const float4*)&pb[BK];  fb1 = *(const float4*)&pb[BK + 4];
    __syncthreads();

    for (int c = 0; c < KD / BK; c++) {
        const int cur = c & 1, nxt = cur ^ 1;
        if (c < 15) {
            uint4 u;
            u.x = f2tf(fa0.x); u.y = f2tf(fa0.y); u.z = f2tf(fa0.z); u.w = f2tf(fa0.w);
            *(uint4*)&As[nxt][srow * SPAD + sk4] = u;
            u.x = f2tf(fa1.x); u.y = f2tf(fa1.y); u.z = f2tf(fa1.z); u.w = f2tf(fa1.w);
            *(uint4*)&As[nxt][srow * SPAD + sk4 + 4] = u;
            u.x = f2tf(fb0.x); u.y = f2tf(fb0.y); u.z = f2tf(fb0.z); u.w = f2tf(fb0.w);
            *(uint4*)&Bs[nxt][srow * SPAD + sk4] = u;
            u.x = f2tf(fb1.x); u.y = f2tf(fb1.y); u.z = f2tf(fb1.z); u.w = f2tf(fb1.w);
            *(uint4*)&Bs[nxt][srow * SPAD + sk4 + 4] = u;
            if (c < 14) {
                const int ko = (c + 2) * BK;
                fa0 = *(const float4*)&pa[ko];  fa1 = *(const float4*)&pa[ko + 4];
                fb0 = *(const float4*)&pb[ko];  fb1 = *(const float4*)&pb[ko + 4];
            }
        }
#pragma unroll
        for (int ks = 0; ks < 2; ks++) {
            const int kb = ks * 8;
            unsigned a[2][4], b[8][2];
#pragma unroll
            for (int mt = 0; mt < 2; mt++) {
                const int r = wm + mt * 16 + g;
                a[mt][0] = As[cur][r * SPAD + kb + tig];
                a[mt][1] = As[cur][(r + 8) * SPAD + kb + tig];
                a[mt][2] = As[cur][r * SPAD + kb + tig + 4];
                a[mt][3] = As[cur][(r + 8) * SPAD + kb + tig + 4];
            }
#pragma unroll
            for (int nt = 0; nt < 8; nt++) {
                const int n = wn + nt * 8 + g;
                b[nt][0] = Bs[cur][n * SPAD + kb + tig];
                b[nt][1] = Bs[cur][n * SPAD + kb + tig + 4];
            }
#pragma unroll
            for (int mt = 0; mt < 2; mt++)
#pragma unroll
                for (int nt = 0; nt < 8; nt++)
                    mma_tf32(acc[mt][nt],
                             a[mt][0], a[mt][1], a[mt][2], a[mt][3],
                             b[nt][0], b[nt][1]);
        }
        __syncthreads();
    }

    if (is_kp) {
        const int bb = n0 >> 8;
        const int t0 = n0 & 255;
        __half* C = g_kph + (size_t)bb * DD * TH;
#pragma unroll
        for (int mt = 0; mt < 2; mt++) {
            const int row = m0 + wm + mt * 16 + g;
#pragma unroll
            for (int nt = 0; nt < 8; nt++) {
                const int col = t0 + wn + nt * 8 + 2 * tig;
                *(__half2*)&C[(size_t)row * TH + col] =
                    __floats2half2_rn(acc[mt][nt][0], acc[mt][nt][1]);
                *(__half2*)&C[(size_t)(row + 8) * TH + col] =
                    __floats2half2_rn(acc[mt][nt][2], acc[mt][nt][3]);
            }
        }
    } else {
#pragma unroll
        for (int mt = 0; mt < 2; mt++) {
            const int row = m0 + wm + mt * 16 + g;
#pragma unroll
            for (int nt = 0; nt < 8; nt++) {
                const int col = n0 + wn + nt * 8 + 2 * tig;
                *(__half2*)&g_qph[(size_t)row * DD + col] =
                    __floats2half2_rn(acc[mt][nt][0], acc[mt][nt][1]);
                *(__half2*)&g_qph[(size_t)(row + 8) * DD + col] =
                    __floats2half2_rn(acc[mt][nt][2], acc[mt][nt][3]);
            }
        }
    }
}

// ---------------------------------------------------------------------------
// Kernel 2: scores + softmax + context. grid (TQ/2, B) = 1024 blocks, 256
// threads, 2 queries/block.
// Score: thread owns t-pair (ti = tid&127), d-rows split across halves
// (half = tid>>7). Per 4-d window, sq0/sq1/sv2 hoisted via 3 LDS.128 ->
// inner d-step = LDS kt + 2 HADD2 + 2 MUFU + 2 HFMA2 (7 issues).
// Context: thread owns i-PAIR (i = 2ti, 2ti+1), t-rows split across halves,
// f32 accumulation (unchanged math). Cross-half combines via part[] smem.
// ---------------------------------------------------------------------------
#define HPAD 264   // halves per staged row (33 uint4)

__global__ __launch_bounds__(256) void attn_kernel(
    const float* __restrict__ v, float* __restrict__ out)
{
    __shared__ __align__(16) __half stage[2][16][HPAD];  // 16.9 KB
    __shared__ __align__(16) float sc[2][256];           // scores -> exp
    __shared__ __align__(16) __half2 sq0[256];           // {q0,q0} per d
    __shared__ __align__(16) __half2 sq1[256];           // {q1,q1} per d
    __shared__ __align__(16) __half2 sv2[256];           // {v,v} per d (f16)
    __shared__ __align__(16) float part[4][128];         // cross-half partials
    __shared__ float sinv[2];

    const int b    = blockIdx.y;
    const int q0   = blockIdx.x * 2;
    const int tid  = threadIdx.x;
    const int warp = tid >> 5;
    const int lane = tid & 31;
    const int ti   = tid & 127;     // t-pair / i-pair index
    const int half = tid >> 7;      // row half
    const int rb   = half * 8;      // row base within chunk

    sv2[tid] = __float2half2_rn(v[tid]);
    sq0[tid] = __half2half2(g_qph[(size_t)(b * TQ + q0 + 0) * DD + tid]);
    sq1[tid] = __half2half2(g_qph[(size_t)(b * TQ + q0 + 1) * DD + tid]);

    const uint4* kp4 = (const uint4*)(g_kph + (size_t)b * DD * TH);   // 32 u4/row

    // ---- scores: s[q][t] = sum_d v[d] * tanh_f16(qp[q][d] + kp[d][t]) ----
    float a00 = 0.f, a01 = 0.f, a10 = 0.f, a11 = 0.f;  // [q][t-pos]
    uint4 pf[2];

    // prologue: chunk 0 -> buf0, prefetch chunk 1
#pragma unroll
    for (int s = 0; s < 2; s++) {
        int idx = tid + s * 256, r = idx >> 5, cc = idx & 31;
        pf[s] = kp4[r * 32 + cc];
    }
#pragma unroll
    for (int s = 0; s < 2; s++) {
        int idx = tid + s * 256, r = idx >> 5, cc = idx & 31;
        *(uint4*)&stage[0][r][cc * 8] = pf[s];
    }
#pragma unroll
    for (int s = 0; s < 2; s++) {
        int idx = tid + s * 256, r = idx >> 5, cc = idx & 31;
        pf[s] = kp4[(16 + r) * 32 + cc];
    }
    __syncthreads();

    for (int c = 0; c < 16; c++) {
        const int cur = c & 1, nxt = cur ^ 1;
        if (c < 15) {
#pragma unroll
            for (int s = 0; s < 2; s++) {
                int idx = tid + s * 256, r = idx >> 5, cc = idx & 31;
                *(uint4*)&stage[nxt][r][cc * 8] = pf[s];
            }
            if (c < 14) {
                const int d0n = (c + 2) * 16;
#pragma unroll
                for (int s = 0; s < 2; s++) {
                    int idx = tid + s * 256, r = idx >> 5, cc = idx & 31;
                    pf[s] = kp4[(d0n + r) * 32 + cc];
                }
            }
        }
        const int d0 = c * 16;
#pragma unroll
        for (int w = 0; w < 2; w++) {
            const int db = rb + w * 4;          // this thread's window base
            __half2 q0r[4], q1r[4], vr[4];
            *(uint4*)q0r = *(const uint4*)&sq0[d0 + db];   // 16B-aligned
            *(uint4*)q1r = *(const uint4*)&sq1[d0 + db];
            *(uint4*)vr  = *(const uint4*)&sv2[d0 + db];
            __half2 h0, h1;
            {
                __half2 kt = *(const __half2*)&stage[cur][db][2 * ti];
                h0 = __hmul2(vr[0], tanh_f16x2(__hadd2(q0r[0], kt)));
                h1 = __hmul2(vr[0], tanh_f16x2(__hadd2(q1r[0], kt)));
            }
#pragma unroll
            for (int j = 1; j < 4; j++) {
                __half2 kt = *(const __half2*)&stage[cur][db + j][2 * ti];
                h0 = __hfma2(vr[j], tanh_f16x2(__hadd2(q0r[j], kt)), h0);
                h1 = __hfma2(vr[j], tanh_f16x2(__hadd2(q1r[j], kt)), h1);
            }
            float2 f0 = __half22float2(h0);
            float2 f1 = __half22float2(h1);
            a00 += f0.x; a01 += f0.y;
            a10 += f1.x; a11 += f1.y;
        }
        __syncthreads();
    }

    // cross-half combine: half 1 publishes, half 0 reduces + writes sc
    if (half) {
        part[0][ti] = a00; part[1][ti] = a01;
        part[2][ti] = a10; part[3][ti] = a11;
    }
    __syncthreads();
    if (!half) {
        sc[0][2 * ti + 0] = a00 + part[0][ti];
        sc[0][2 * ti + 1] = a01 + part[1][ti];
        sc[1][2 * ti + 0] = a10 + part[2][ti];
        sc[1][2 * ti + 1] = a11 + part[3][ti];
    }
    __syncthreads();

    // ---- softmax (unnormalized): warps 0-1, one query each ----
    if (warp < 2) {
        float ls[8];
        float m = -1e30f;
#pragma unroll
        for (int j = 0; j < 8; j++) {
            ls[j] = sc[warp][j * 32 + lane];
            m = fmaxf(m, ls[j]);
        }
#pragma unroll
        for (int o = 16; o; o >>= 1) m = fmaxf(m, __shfl_xor_sync(0xffffffffu, m, o));
        float ssum = 0.f;
#pragma unroll
        for (int j = 0; j < 8; j++) {
            ls[j] = __expf(ls[j] - m);
            ssum += ls[j];
        }
#pragma unroll
        for (int o = 16; o; o >>= 1) ssum += __shfl_xor_sync(0xffffffffu, ssum, o);
#pragma unroll
        for (int j = 0; j < 8; j++) sc[warp][j * 32 + lane] = ls[j];
        if (lane == 0) sinv[warp] = 1.f / ssum;
    }

    // ---- context: thread owns i-pair (2ti, 2ti+1); t-rows split by half ----
    float c00 = 0.f, c01 = 0.f;   // q0: i, i+1
    float c10 = 0.f, c11 = 0.f;   // q1: i, i+1
    const uint4* kb4 = (const uint4*)(g_keysh + (size_t)b * TH * DIN);

#pragma unroll
    for (int s = 0; s < 2; s++) {
        int idx = tid + s * 256, r = idx >> 5, cc = idx & 31;
        pf[s] = kb4[r * 32 + cc];
    }
    __syncthreads();   // orders softmax writes for all warps
#pragma unroll
    for (int s = 0; s < 2; s++) {
        int idx = tid + s * 256, r = idx >> 5, cc = idx & 31;
        *(uint4*)&stage[0][r][cc * 8] = pf[s];
    }
#pragma unroll
    for (int s = 0; s < 2; s++) {
        int idx = tid + s * 256, r = idx >> 5, cc = idx & 31;
        pf[s] = kb4[(16 + r) * 32 + cc];
    }
    __syncthreads();

    for (int c = 0; c < 16; c++) {
        const int cur = c & 1, nxt = cur ^ 1;
        if (c < 15) {
#pragma unroll
            for (int s = 0; s < 2; s++) {
                int idx = tid + s * 256, r = idx >> 5, cc = idx & 31;
                *(uint4*)&stage[nxt][r][cc * 8] = pf[s];
            }
            if (c < 14) {
                const int t0n = (c + 2) * 16;
#pragma unroll
                for (int s = 0; s < 2; s++) {
                    int idx = tid + s * 256, r = idx >> 5, cc = idx & 31;
                    pf[s] = kb4[(t0n + r) * 32 + cc];
                }
            }
        }
        const int t0 = c * 16;
#pragma unroll
        for (int j = 0; j < 8; j++) {
            const int tt = rb + j;                       // this thread's t-row
            __half2 kt = *(const __half2*)&stage[cur][tt][2 * ti];
            float2 kf = __half22float2(kt);
            float e0 = sc[0][t0 + tt];                   // broadcast
            float e1 = sc[1][t0 + tt];
            c00 = fmaf(e0, kf.x, c00);
            c01 = fmaf(e0, kf.y, c01);
            c10 = fmaf(e1, kf.x, c10);
            c11 = fmaf(e1, kf.y, c11);
        }
        __syncthreads();
    }

    // cross-half combine + output (half 0 writes)
    if (half) {
        part[0][ti] = c00; part[1][ti] = c01;
        part[2][ti] = c10; part[3][ti] = c11;
    }
    __syncthreads();
    if (!half) {
        float i0 = sinv[0], i1 = sinv[1];
        float2 o0 = make_float2((c00 + part[0][ti]) * i0,
                                (c01 + part[1][ti]) * i0);
        float2 o1 = make_float2((c10 + part[2][ti]) * i1,
                                (c11 + part[3][ti]) * i1);
        *(float2*)&out[(size_t)(b * TQ + q0 + 0) * DIN + 2 * ti] = o0;
        *(float2*)&out[(size_t)(b * TQ + q0 + 1) * DIN + 2 * ti] = o1;
    }
}

// ---------------------------------------------------------------------------
// Launch. Inputs (metadata order): inputs, state, w1, w2, v, batch_size.
// Output: (B*TQ, DIN) float32.
// ---------------------------------------------------------------------------
extern "C" void kernel_launch(void* const* d_in, const int* in_sizes, int n_in,
                              void* d_out, int out_size)
{
    const float* inputs = (const float*)d_in[0];
    const float* state  = (const float*)d_in[1];
    const float* w1     = (const float*)d_in[2];
    const float* w2     = (const float*)d_in[3];
    const float* v      = (const float*)d_in[4];
    float* out = (float*)d_out;
    (void)in_sizes; (void)n_in; (void)out_size;

    proj_tc<<<192, 256>>>(inputs, state, w1, w2);   // 160 GEMM + 32 keys-f16 riders

    dim3 g2(TQ / 2, B_);       // (32, 32) = 1024 blocks, 2 queries each
    attn_kernel<<<g2, 256>>>(v, out);
}